// round 3
// baseline (speedup 1.0000x reference)
#include <cuda_runtime.h>
#include <cuda_fp16.h>
#include <mma.h>
using namespace nvcuda;

// Problem constants
#define MAXN 50000
#define MAXE 400000
#define MAXTOT (MAXN + MAXE)
#define GAT_EPS 1e-5f

// ------------------------- scratch (device globals) ------------------------
__device__ float g_xw [MAXN * 128];
__device__ float g_aux[MAXN * 128];
__device__ float g_h1 [MAXN * 128];
__device__ float g_h2 [MAXN * 128];
__device__ float g_agg[MAXN * 128];
__device__ float g_es [MAXN * 4];
__device__ float g_ed [MAXN * 4];
__device__ int   g_cnt[MAXN];
__device__ int   g_off[MAXN + 1];
__device__ int   g_cur[MAXN];
__device__ int   g_csr[MAXTOT];

// ------------------------- CSR build ---------------------------------------
__global__ void zcnt_kernel(int n) {
    int i = blockIdx.x * blockDim.x + threadIdx.x;
    if (i < n) g_cnt[i] = 0;
}

__global__ void histo_kernel(const int* __restrict__ dst, int E, int n) {
    int i = blockIdx.x * blockDim.x + threadIdx.x;
    if (i >= E + n) return;
    int dd = (i < E) ? dst[i] : (i - E);
    atomicAdd(&g_cnt[dd], 1);
}

__global__ void scan_kernel(int n) {
    __shared__ int s[1024];
    __shared__ int carry_s;
    if (threadIdx.x == 0) carry_s = 0;
    __syncthreads();
    for (int base = 0; base < n; base += 1024) {
        int i = base + threadIdx.x;
        int v = (i < n) ? g_cnt[i] : 0;
        s[threadIdx.x] = v;
        __syncthreads();
        #pragma unroll
        for (int d = 1; d < 1024; d <<= 1) {
            int t = (threadIdx.x >= d) ? s[threadIdx.x - d] : 0;
            __syncthreads();
            s[threadIdx.x] += t;
            __syncthreads();
        }
        int c = carry_s;
        int exc = c + s[threadIdx.x] - v;
        if (i < n) { g_off[i] = exc; g_cur[i] = exc; }
        __syncthreads();
        if (threadIdx.x == 1023) carry_s = c + s[1023];
        __syncthreads();
    }
    if (threadIdx.x == 0) g_off[n] = carry_s;
}

__global__ void scatter_kernel(const int* __restrict__ src, const int* __restrict__ dst,
                               int E, int n) {
    int i = blockIdx.x * blockDim.x + threadIdx.x;
    if (i >= E + n) return;
    int ss, dd;
    if (i < E) { ss = src[i]; dd = dst[i]; }
    else       { ss = dd = i - E; }
    int p = atomicAdd(&g_cur[dd], 1);
    g_csr[p] = ss;
}

// ------------------------- WMMA fp16x3 GEMM: C[M,128] = A[M,128] @ B[128,128]
// fp16 split: hi = h(x), lo = h(x - hi). C = AhBh + AlBh + AhBl (missing AlBl ~2^-22).
__global__ void __launch_bounds__(256)
hgemm128(const float* __restrict__ A, const float* __restrict__ Bw,
         float* __restrict__ C, int M) {
    __shared__ __half sAh[128 * 16], sAl[128 * 16];
    __shared__ __half sBh[16 * 128], sBl[16 * 128];
    int tid = threadIdx.x;
    int wid = tid >> 5;
    int wm = wid & 3, wn = wid >> 2;          // 4 warps in M, 2 in N
    int row0 = blockIdx.x * 128;

    wmma::fragment<wmma::accumulator, 16, 16, 16, float> acc[2][4];
    #pragma unroll
    for (int i = 0; i < 2; i++)
        #pragma unroll
        for (int j = 0; j < 4; j++)
            wmma::fill_fragment(acc[i][j], 0.f);

    for (int k0 = 0; k0 < 128; k0 += 16) {
        // A chunk [128 x 16] fp32 -> hi/lo fp16
        #pragma unroll
        for (int it = 0; it < 8; it++) {
            int idx = tid + it * 256;
            int r = idx >> 4, c = idx & 15;
            int gr = row0 + r;
            float v = (gr < M) ? A[(size_t)gr * 128 + k0 + c] : 0.f;
            __half h = __float2half_rn(v);
            sAh[idx] = h;
            sAl[idx] = __float2half_rn(v - __half2float(h));
        }
        // B chunk [16 x 128]
        #pragma unroll
        for (int it = 0; it < 8; it++) {
            int idx = tid + it * 256;
            int r = idx >> 7, c = idx & 127;
            float v = Bw[(size_t)(k0 + r) * 128 + c];
            __half h = __float2half_rn(v);
            sBh[idx] = h;
            sBl[idx] = __float2half_rn(v - __half2float(h));
        }
        __syncthreads();

        wmma::fragment<wmma::matrix_a, 16, 16, 16, __half, wmma::row_major> ah[2], al[2];
        #pragma unroll
        for (int i = 0; i < 2; i++) {
            wmma::load_matrix_sync(ah[i], sAh + (wm * 32 + i * 16) * 16, 16);
            wmma::load_matrix_sync(al[i], sAl + (wm * 32 + i * 16) * 16, 16);
        }
        #pragma unroll
        for (int j = 0; j < 4; j++) {
            wmma::fragment<wmma::matrix_b, 16, 16, 16, __half, wmma::row_major> bh, bl;
            wmma::load_matrix_sync(bh, sBh + wn * 64 + j * 16, 128);
            wmma::load_matrix_sync(bl, sBl + wn * 64 + j * 16, 128);
            #pragma unroll
            for (int i = 0; i < 2; i++) {
                wmma::mma_sync(acc[i][j], ah[i], bh, acc[i][j]);
                wmma::mma_sync(acc[i][j], al[i], bh, acc[i][j]);
                wmma::mma_sync(acc[i][j], ah[i], bl, acc[i][j]);
            }
        }
        __syncthreads();
    }

    // M = 50000 is a multiple of 16, so 16-row tiles are all-in or all-out
    #pragma unroll
    for (int i = 0; i < 2; i++) {
        int gr = row0 + wm * 32 + i * 16;
        if (gr < M) {
            #pragma unroll
            for (int j = 0; j < 4; j++)
                wmma::store_matrix_sync(C + (size_t)gr * 128 + wn * 64 + j * 16,
                                        acc[i][j], 128, wmma::mem_row_major);
        }
    }
}

// ------------------------- small GEMM: C[M,40] = A[M,128] @ B[128,40] ------
__global__ void gemm40(const float* __restrict__ A, const float* __restrict__ B,
                       float* __restrict__ C, int M) {
    __shared__ float Ws[128 * 40];
    for (int i = threadIdx.x; i < 128 * 40; i += blockDim.x) Ws[i] = B[i];
    __syncthreads();
    int row  = blockIdx.x * 8 + (threadIdx.x >> 5);
    int lane = threadIdx.x & 31;
    if (row >= M) return;
    const float* a = A + (size_t)row * 128;
    float acc1 = 0.f, acc2 = 0.f;
    #pragma unroll 8
    for (int k = 0; k < 128; k++) {
        float av = __ldg(a + k);
        acc1 += av * Ws[k * 40 + lane];
        if (lane < 8) acc2 += av * Ws[k * 40 + 32 + lane];
    }
    C[(size_t)row * 40 + lane] = acc1;
    if (lane < 8) C[(size_t)row * 40 + 32 + lane] = acc2;
}

// ------------------------- attention logits ---------------------------------
__global__ void dots128(const float* __restrict__ xw,
                        const float* __restrict__ a_s, const float* __restrict__ a_d,
                        int n) {
    int node = blockIdx.x * 8 + (threadIdx.x >> 5);
    if (node >= n) return;
    int lane = threadIdx.x & 31;
    float4 xv  = *(const float4*)(xw + (size_t)node * 128 + lane * 4);
    float4 asv = *(const float4*)(a_s + lane * 4);
    float4 adv = *(const float4*)(a_d + lane * 4);
    float ps = xv.x * asv.x + xv.y * asv.y + xv.z * asv.z + xv.w * asv.w;
    float pd = xv.x * adv.x + xv.y * adv.y + xv.z * adv.z + xv.w * adv.w;
    ps += __shfl_xor_sync(0xffffffffu, ps, 1);
    ps += __shfl_xor_sync(0xffffffffu, ps, 2);
    ps += __shfl_xor_sync(0xffffffffu, ps, 4);
    pd += __shfl_xor_sync(0xffffffffu, pd, 1);
    pd += __shfl_xor_sync(0xffffffffu, pd, 2);
    pd += __shfl_xor_sync(0xffffffffu, pd, 4);
    if ((lane & 7) == 0) {
        int h = lane >> 3;
        g_es[node * 4 + h] = ps;
        g_ed[node * 4 + h] = pd;
    }
}

__global__ void dots40(const float* __restrict__ xw,
                       const float* __restrict__ a_s, const float* __restrict__ a_d,
                       int n) {
    int node = blockIdx.x * 8 + (threadIdx.x >> 5);
    if (node >= n) return;
    int lane = threadIdx.x & 31;
    float x1 = xw[(size_t)node * 40 + lane];
    float x2 = (lane < 8) ? xw[(size_t)node * 40 + 32 + lane] : 0.f;
    float ps = x1 * a_s[lane] + ((lane < 8) ? x2 * a_s[32 + lane] : 0.f);
    float pd = x1 * a_d[lane] + ((lane < 8) ? x2 * a_d[32 + lane] : 0.f);
    #pragma unroll
    for (int o = 16; o; o >>= 1) {
        ps += __shfl_xor_sync(0xffffffffu, ps, o);
        pd += __shfl_xor_sync(0xffffffffu, pd, o);
    }
    if (lane == 0) { g_es[node] = ps; g_ed[node] = pd; }
}

// ------------------------- GAT aggregation (warp/node, online softmax) ------
__global__ void agg128(const float* __restrict__ xw, float* __restrict__ out, int n) {
    int node = blockIdx.x * 8 + (threadIdx.x >> 5);
    if (node >= n) return;
    int lane = threadIdx.x & 31;
    int head = lane >> 3;
    float ed = g_ed[node * 4 + head];
    int s = g_off[node], e = g_off[node + 1];
    float m = -1e30f, d = 0.f;
    float4 acc = make_float4(0.f, 0.f, 0.f, 0.f);
    for (int i = s; i < e; i++) {
        int u = g_csr[i];
        float ev = g_es[u * 4 + head] + ed;
        ev = ev > 0.f ? ev : 0.2f * ev;
        float4 xv = *(const float4*)(xw + (size_t)u * 128 + lane * 4);
        if (ev <= m) {
            float w = __expf(ev - m);
            d += w;
            acc.x += w * xv.x; acc.y += w * xv.y;
            acc.z += w * xv.z; acc.w += w * xv.w;
        } else {
            float w = __expf(m - ev);
            d = d * w + 1.f;
            acc.x = acc.x * w + xv.x; acc.y = acc.y * w + xv.y;
            acc.z = acc.z * w + xv.z; acc.w = acc.w * w + xv.w;
            m = ev;
        }
    }
    float inv = 1.f / d;
    float4 o = make_float4(acc.x * inv, acc.y * inv, acc.z * inv, acc.w * inv);
    *(float4*)(out + (size_t)node * 128 + lane * 4) = o;
}

__global__ void agg40(const float* __restrict__ xw, const float* __restrict__ bias,
                      float* __restrict__ out, int n) {
    int node = blockIdx.x * 8 + (threadIdx.x >> 5);
    if (node >= n) return;
    int lane = threadIdx.x & 31;
    float ed = g_ed[node];
    int s = g_off[node], e = g_off[node + 1];
    float m = -1e30f, d = 0.f, a1 = 0.f, a2 = 0.f;
    for (int i = s; i < e; i++) {
        int u = g_csr[i];
        float ev = g_es[u] + ed;
        ev = ev > 0.f ? ev : 0.2f * ev;
        float x1 = xw[(size_t)u * 40 + lane];
        float x2 = (lane < 8) ? xw[(size_t)u * 40 + 32 + lane] : 0.f;
        if (ev <= m) {
            float w = __expf(ev - m);
            d += w; a1 += w * x1; a2 += w * x2;
        } else {
            float w = __expf(m - ev);
            d = d * w + 1.f; a1 = a1 * w + x1; a2 = a2 * w + x2;
            m = ev;
        }
    }
    float inv = 1.f / d;
    out[(size_t)node * 40 + lane] = a1 * inv + bias[lane];
    if (lane < 8) out[(size_t)node * 40 + 32 + lane] = a2 * inv + bias[32 + lane];
}

// ------------------------- bias + BN(eval) + residual + ELU -----------------
__global__ void postk(const float* __restrict__ agg, const float* __restrict__ bias,
                      const float* __restrict__ g, const float* __restrict__ be,
                      const float* __restrict__ mean, const float* __restrict__ var,
                      const float* __restrict__ res, float* __restrict__ out, int total) {
    int i = blockIdx.x * blockDim.x + threadIdx.x;
    if (i >= total) return;
    int c = i & 127;
    float xv = agg[i] + bias[c];
    xv = (xv - mean[c]) * rsqrtf(var[c] + GAT_EPS) * g[c] + be[c] + res[i];
    out[i] = xv > 0.f ? xv : expm1f(xv);
}

// ------------------------- launch ------------------------------------------
extern "C" void kernel_launch(void* const* d_in, const int* in_sizes, int n_in,
                              void* d_out, int out_size) {
    const float* x    = (const float*)d_in[0];
    const int*   ei   = (const int*)  d_in[1];
    const float* W1   = (const float*)d_in[2];
    const float* as1  = (const float*)d_in[3];
    const float* ad1  = (const float*)d_in[4];
    const float* b1   = (const float*)d_in[5];
    const float* W2   = (const float*)d_in[6];
    const float* as2  = (const float*)d_in[7];
    const float* ad2  = (const float*)d_in[8];
    const float* b2   = (const float*)d_in[9];
    const float* W3   = (const float*)d_in[10];
    const float* as3  = (const float*)d_in[11];
    const float* ad3  = (const float*)d_in[12];
    const float* b3   = (const float*)d_in[13];
    const float* Wres = (const float*)d_in[14];
    const float* g1   = (const float*)d_in[15];
    const float* be1  = (const float*)d_in[16];
    const float* m1   = (const float*)d_in[17];
    const float* v1   = (const float*)d_in[18];
    const float* g2   = (const float*)d_in[19];
    const float* be2  = (const float*)d_in[20];
    const float* m2   = (const float*)d_in[21];
    const float* v2   = (const float*)d_in[22];

    int n = in_sizes[0] / 128;
    int E = in_sizes[1] / 2;
    const int* src = ei;
    const int* dst = ei + E;
    int tot = E + n;

    float *p_xw, *p_aux, *p_h1, *p_h2, *p_agg;
    cudaGetSymbolAddress((void**)&p_xw,  g_xw);
    cudaGetSymbolAddress((void**)&p_aux, g_aux);
    cudaGetSymbolAddress((void**)&p_h1,  g_h1);
    cudaGetSymbolAddress((void**)&p_h2,  g_h2);
    cudaGetSymbolAddress((void**)&p_agg, g_agg);

    int nb_gemm = (n + 127) / 128;
    int nb_warp = (n + 7) / 8;
    int nb_elem = (n * 128 + 255) / 256;

    // CSR by dst (includes self loops)
    zcnt_kernel   <<<(n + 255) / 256, 256>>>(n);
    histo_kernel  <<<(tot + 255) / 256, 256>>>(dst, E, n);
    scan_kernel   <<<1, 1024>>>(n);
    scatter_kernel<<<(tot + 255) / 256, 256>>>(src, dst, E, n);

    // ---- layer 1 ----
    hgemm128<<<nb_gemm, 256>>>(x, W1,   p_xw,  n);
    hgemm128<<<nb_gemm, 256>>>(x, Wres, p_aux, n);
    dots128 <<<nb_warp, 256>>>(p_xw, as1, ad1, n);
    agg128  <<<nb_warp, 256>>>(p_xw, p_agg, n);
    postk   <<<nb_elem, 256>>>(p_agg, b1, g1, be1, m1, v1, p_aux, p_h1, n * 128);

    // ---- layer 2 ----
    hgemm128<<<nb_gemm, 256>>>(p_h1, W2, p_xw, n);
    dots128 <<<nb_warp, 256>>>(p_xw, as2, ad2, n);
    agg128  <<<nb_warp, 256>>>(p_xw, p_agg, n);
    postk   <<<nb_elem, 256>>>(p_agg, b2, g2, be2, m2, v2, p_h1, p_h2, n * 128);

    // ---- layer 3 ----
    gemm40<<<nb_warp, 256>>>(p_h2, W3, p_aux, n);
    dots40<<<nb_warp, 256>>>(p_aux, as3, ad3, n);
    agg40 <<<nb_warp, 256>>>(p_aux, b3, (float*)d_out, n);
}

// round 4
// speedup vs baseline: 1.2441x; 1.2441x over previous
#include <cuda_runtime.h>
#include <cuda_fp16.h>
#include <mma.h>
using namespace nvcuda;

// Problem constants
#define MAXN 50000
#define MAXE 400000
#define MAXTOT (MAXN + MAXE)
#define GAT_EPS 1e-5f

// ------------------------- scratch (device globals) ------------------------
__device__ float g_xw  [MAXN * 128];
__device__ float g_aux [MAXN * 128];
__device__ float g_h1  [MAXN * 128];
__device__ float g_h2  [MAXN * 128];
__device__ float g_es  [MAXN * 4];
__device__ float g_ed  [MAXN * 4];
__device__ float g_rm  [MAXN * 4];
__device__ float g_rinv[MAXN * 4];
__device__ float g_eraw[(MAXTOT + 8) * 4];
__device__ int   g_cnt [MAXN];
__device__ int   g_off [MAXN + 1];
__device__ int   g_cur [MAXN];
__device__ int   g_csr [MAXTOT + 8];
__device__ int   g_bsum[64];
__device__ int   g_boff[64];
__device__ __half g_Bh[16384];
__device__ __half g_Bl[16384];

// ------------------------- CSR build ---------------------------------------
__global__ void zcnt_kernel(int n) {
    int i = blockIdx.x * blockDim.x + threadIdx.x;
    if (i < n) g_cnt[i] = 0;
}

__global__ void histo_kernel(const int* __restrict__ dst, int E, int n) {
    int i = blockIdx.x * blockDim.x + threadIdx.x;
    if (i >= E + n) return;
    int dd = (i < E) ? dst[i] : (i - E);
    atomicAdd(&g_cnt[dd], 1);
}

// multi-block scan: phase 1 — per-block (1024 elems) exclusive scan + block sum
__global__ void scan1_kernel(int n) {
    __shared__ int wsum[8];
    int tid = threadIdx.x;
    int base = blockIdx.x * 1024 + tid * 4;
    int c0 = (base + 0 < n) ? g_cnt[base + 0] : 0;
    int c1 = (base + 1 < n) ? g_cnt[base + 1] : 0;
    int c2 = (base + 2 < n) ? g_cnt[base + 2] : 0;
    int c3 = (base + 3 < n) ? g_cnt[base + 3] : 0;
    int t = c0 + c1 + c2 + c3;
    int lane = tid & 31, wid = tid >> 5;
    int incl = t;
    #pragma unroll
    for (int o = 1; o < 32; o <<= 1) {
        int v = __shfl_up_sync(0xffffffffu, incl, o);
        if (lane >= o) incl += v;
    }
    if (lane == 31) wsum[wid] = incl;
    __syncthreads();
    if (tid == 0) {
        int r = 0;
        #pragma unroll
        for (int k = 0; k < 8; k++) { int v = wsum[k]; wsum[k] = r; r += v; }
        g_bsum[blockIdx.x] = r;
    }
    __syncthreads();
    int run = wsum[wid] + incl - t;
    if (base + 0 < n) g_off[base + 0] = run; run += c0;
    if (base + 1 < n) g_off[base + 1] = run; run += c1;
    if (base + 2 < n) g_off[base + 2] = run; run += c2;
    if (base + 3 < n) g_off[base + 3] = run;
}

// phase 2 — single warp scans block sums (nb <= 64)
__global__ void scan2_kernel(int nb, int n) {
    int lane = threadIdx.x;
    int v0 = (lane < nb) ? g_bsum[lane] : 0;
    int v1 = (32 + lane < nb) ? g_bsum[32 + lane] : 0;
    int i0 = v0;
    #pragma unroll
    for (int o = 1; o < 32; o <<= 1) {
        int q = __shfl_up_sync(0xffffffffu, i0, o);
        if (lane >= o) i0 += q;
    }
    int tot0 = __shfl_sync(0xffffffffu, i0, 31);
    int i1 = v1;
    #pragma unroll
    for (int o = 1; o < 32; o <<= 1) {
        int q = __shfl_up_sync(0xffffffffu, i1, o);
        if (lane >= o) i1 += q;
    }
    i1 += tot0;
    if (lane < nb) g_boff[lane] = i0 - v0;
    if (32 + lane < nb) g_boff[32 + lane] = i1 - v1;
    int grand = __shfl_sync(0xffffffffu, i1, 31);
    if (lane == 0) g_off[n] = grand;
}

// phase 3 — add block offsets, init cursors
__global__ void scan3_kernel(int n) {
    int i = blockIdx.x * blockDim.x + threadIdx.x;
    if (i >= n) return;
    int o = g_off[i] + g_boff[i >> 10];
    g_off[i] = o;
    g_cur[i] = o;
}

__global__ void scatter_kernel(const int* __restrict__ src, const int* __restrict__ dst,
                               int E, int n) {
    int i = blockIdx.x * blockDim.x + threadIdx.x;
    if (i >= E + n) return;
    int ss, dd;
    if (i < E) { ss = src[i]; dd = dst[i]; }
    else       { ss = dd = i - E; }
    int p = atomicAdd(&g_cur[dd], 1);
    g_csr[p] = ss;
}

// ------------------------- B preconversion (fp32 -> fp16 hi/lo) ------------
__global__ void preB_kernel(const float* __restrict__ W) {
    int i = blockIdx.x * blockDim.x + threadIdx.x;
    if (i >= 16384) return;
    float v = W[i];
    __half h = __float2half_rn(v);
    g_Bh[i] = h;
    g_Bl[i] = __float2half_rn(v - __half2float(h));
}

// ------------------------- WMMA fp16x3 GEMM: C[M,128] = A[M,128] @ B[128,128]
__global__ void __launch_bounds__(256)
hgemm128(const float* __restrict__ A, float* __restrict__ C, int M) {
    __shared__ __half sAh[128 * 32], sAl[128 * 32];
    __shared__ __half sBh[32 * 128], sBl[32 * 128];
    int tid = threadIdx.x;
    int wid = tid >> 5;
    int wm = wid & 3, wn = wid >> 2;
    int row0 = blockIdx.x * 128;

    wmma::fragment<wmma::accumulator, 16, 16, 16, float> acc[2][4];
    #pragma unroll
    for (int i = 0; i < 2; i++)
        #pragma unroll
        for (int j = 0; j < 4; j++)
            wmma::fill_fragment(acc[i][j], 0.f);

    for (int kc = 0; kc < 4; kc++) {
        // A chunk [128 x 32] fp32 -> hi/lo fp16
        #pragma unroll
        for (int it = 0; it < 16; it++) {
            int idx = tid + it * 256;
            int r = idx >> 5, c = idx & 31;
            int gr = row0 + r;
            float v = (gr < M) ? A[(size_t)gr * 128 + kc * 32 + c] : 0.f;
            __half h = __float2half_rn(v);
            sAh[idx] = h;
            sAl[idx] = __float2half_rn(v - __half2float(h));
        }
        // B chunk: contiguous 8KB copies from preconverted halves
        {
            const unsigned* bh = (const unsigned*)g_Bh + kc * 2048;
            const unsigned* bl = (const unsigned*)g_Bl + kc * 2048;
            unsigned* dh = (unsigned*)sBh;
            unsigned* dl = (unsigned*)sBl;
            #pragma unroll
            for (int it = 0; it < 8; it++) {
                int idx = tid + it * 256;
                dh[idx] = bh[idx];
                dl[idx] = bl[idx];
            }
        }
        __syncthreads();

        #pragma unroll
        for (int kk = 0; kk < 2; kk++) {
            wmma::fragment<wmma::matrix_a, 16, 16, 16, __half, wmma::row_major> ah[2], al[2];
            #pragma unroll
            for (int i = 0; i < 2; i++) {
                wmma::load_matrix_sync(ah[i], sAh + (wm * 32 + i * 16) * 32 + kk * 16, 32);
                wmma::load_matrix_sync(al[i], sAl + (wm * 32 + i * 16) * 32 + kk * 16, 32);
            }
            #pragma unroll
            for (int j = 0; j < 4; j++) {
                wmma::fragment<wmma::matrix_b, 16, 16, 16, __half, wmma::row_major> bh, bl;
                wmma::load_matrix_sync(bh, sBh + kk * 16 * 128 + wn * 64 + j * 16, 128);
                wmma::load_matrix_sync(bl, sBl + kk * 16 * 128 + wn * 64 + j * 16, 128);
                #pragma unroll
                for (int i = 0; i < 2; i++) {
                    wmma::mma_sync(acc[i][j], ah[i], bh, acc[i][j]);
                    wmma::mma_sync(acc[i][j], al[i], bh, acc[i][j]);
                    wmma::mma_sync(acc[i][j], ah[i], bl, acc[i][j]);
                }
            }
        }
        __syncthreads();
    }

    #pragma unroll
    for (int i = 0; i < 2; i++) {
        int gr = row0 + wm * 32 + i * 16;
        if (gr < M) {
            #pragma unroll
            for (int j = 0; j < 4; j++)
                wmma::store_matrix_sync(C + (size_t)gr * 128 + wn * 64 + j * 16,
                                        acc[i][j], 128, wmma::mem_row_major);
        }
    }
}

// ------------------------- small GEMM: C[M,40] = A[M,128] @ B[128,40] ------
__global__ void gemm40(const float* __restrict__ A, const float* __restrict__ B,
                       float* __restrict__ C, int M) {
    __shared__ float Ws[128 * 40];
    for (int i = threadIdx.x; i < 128 * 40; i += blockDim.x) Ws[i] = B[i];
    __syncthreads();
    int row  = blockIdx.x * 8 + (threadIdx.x >> 5);
    int lane = threadIdx.x & 31;
    if (row >= M) return;
    const float* a = A + (size_t)row * 128;
    float acc1 = 0.f, acc2 = 0.f;
    #pragma unroll 8
    for (int k = 0; k < 128; k++) {
        float av = __ldg(a + k);
        acc1 += av * Ws[k * 40 + lane];
        if (lane < 8) acc2 += av * Ws[k * 40 + 32 + lane];
    }
    C[(size_t)row * 40 + lane] = acc1;
    if (lane < 8) C[(size_t)row * 40 + 32 + lane] = acc2;
}

// ------------------------- attention logits ---------------------------------
__global__ void dots128(const float* __restrict__ xw,
                        const float* __restrict__ a_s, const float* __restrict__ a_d,
                        int n) {
    int node = blockIdx.x * 8 + (threadIdx.x >> 5);
    if (node >= n) return;
    int lane = threadIdx.x & 31;
    float4 xv  = *(const float4*)(xw + (size_t)node * 128 + lane * 4);
    float4 asv = *(const float4*)(a_s + lane * 4);
    float4 adv = *(const float4*)(a_d + lane * 4);
    float ps = xv.x * asv.x + xv.y * asv.y + xv.z * asv.z + xv.w * asv.w;
    float pd = xv.x * adv.x + xv.y * adv.y + xv.z * adv.z + xv.w * adv.w;
    ps += __shfl_xor_sync(0xffffffffu, ps, 1);
    ps += __shfl_xor_sync(0xffffffffu, ps, 2);
    ps += __shfl_xor_sync(0xffffffffu, ps, 4);
    pd += __shfl_xor_sync(0xffffffffu, pd, 1);
    pd += __shfl_xor_sync(0xffffffffu, pd, 2);
    pd += __shfl_xor_sync(0xffffffffu, pd, 4);
    if ((lane & 7) == 0) {
        int h = lane >> 3;
        g_es[node * 4 + h] = ps;
        g_ed[node * 4 + h] = pd;
    }
}

__global__ void dots40(const float* __restrict__ xw,
                       const float* __restrict__ a_s, const float* __restrict__ a_d,
                       int n) {
    int node = blockIdx.x * 8 + (threadIdx.x >> 5);
    if (node >= n) return;
    int lane = threadIdx.x & 31;
    float x1 = xw[(size_t)node * 40 + lane];
    float x2 = (lane < 8) ? xw[(size_t)node * 40 + 32 + lane] : 0.f;
    float ps = x1 * a_s[lane] + ((lane < 8) ? x2 * a_s[32 + lane] : 0.f);
    float pd = x1 * a_d[lane] + ((lane < 8) ? x2 * a_d[32 + lane] : 0.f);
    #pragma unroll
    for (int o = 16; o; o >>= 1) {
        ps += __shfl_xor_sync(0xffffffffu, ps, o);
        pd += __shfl_xor_sync(0xffffffffu, pd, o);
    }
    if (lane == 0) { g_es[node] = ps; g_ed[node] = pd; }
}

// ------------------------- softmax stats (pass 1) ---------------------------
// warp per node; lanes cover (edge, head) pairs: head = lane>>3, edge = lane&7.
__global__ void stats128(int n) {
    int node = blockIdx.x * 8 + (threadIdx.x >> 5);
    if (node >= n) return;
    int lane = threadIdx.x & 31;
    int head = lane >> 3, esub = lane & 7;
    float ed = g_ed[node * 4 + head];
    int s = g_off[node], e = g_off[node + 1];
    float m = -1e30f, den = 0.f;
    for (int base = s; base < e; base += 8) {
        int i = base + esub;
        bool val = i < e;
        int u = val ? g_csr[i] : 0;
        float ev = g_es[u * 4 + head] + ed;
        ev = ev > 0.f ? ev : 0.2f * ev;          // LeakyReLU(0.2)
        if (!val) ev = -1e30f;
        else g_eraw[i * 4 + head] = ev;          // coalesced 128B per warp
        float gm = ev;
        gm = fmaxf(gm, __shfl_xor_sync(0xffffffffu, gm, 1));
        gm = fmaxf(gm, __shfl_xor_sync(0xffffffffu, gm, 2));
        gm = fmaxf(gm, __shfl_xor_sync(0xffffffffu, gm, 4));
        float nm = fmaxf(m, gm);
        float w = __expf(ev - nm);
        w += __shfl_xor_sync(0xffffffffu, w, 1);
        w += __shfl_xor_sync(0xffffffffu, w, 2);
        w += __shfl_xor_sync(0xffffffffu, w, 4);
        den = den * __expf(m - nm) + w;
        m = nm;
    }
    if (esub == 0) {
        g_rm[node * 4 + head] = m;
        g_rinv[node * 4 + head] = 1.f / den;
    }
}

// ------------------------- weighted gather + BN + res + ELU (pass 2) --------
__global__ void aggpost128(const float* __restrict__ xw,
                           const float* __restrict__ bias,
                           const float* __restrict__ gam, const float* __restrict__ bet,
                           const float* __restrict__ mean, const float* __restrict__ var,
                           const float* __restrict__ res, float* __restrict__ out, int n) {
    int node = blockIdx.x * 8 + (threadIdx.x >> 5);
    if (node >= n) return;
    int lane = threadIdx.x & 31;
    int head = lane >> 3;
    float rm   = g_rm[node * 4 + head];
    float rinv = g_rinv[node * 4 + head];
    int s = g_off[node], e = g_off[node + 1];
    float4 acc = make_float4(0.f, 0.f, 0.f, 0.f);
    int u = g_csr[s];
    float ev = g_eraw[s * 4 + head];
    for (int i = s; i < e; i++) {
        int un = g_csr[i + 1];                   // padded arrays: safe overread
        float evn = g_eraw[(i + 1) * 4 + head];
        float w = __expf(ev - rm);
        float4 xv = *(const float4*)(xw + (size_t)u * 128 + lane * 4);
        acc.x += w * xv.x; acc.y += w * xv.y;
        acc.z += w * xv.z; acc.w += w * xv.w;
        u = un; ev = evn;
    }
    int c = lane * 4;
    float4 b4 = *(const float4*)(bias + c);
    float4 g4 = *(const float4*)(gam + c);
    float4 e4 = *(const float4*)(bet + c);
    float4 m4 = *(const float4*)(mean + c);
    float4 v4 = *(const float4*)(var + c);
    float4 r4 = *(const float4*)(res + (size_t)node * 128 + c);
    float o0 = (acc.x * rinv + b4.x - m4.x) * rsqrtf(v4.x + GAT_EPS) * g4.x + e4.x + r4.x;
    float o1 = (acc.y * rinv + b4.y - m4.y) * rsqrtf(v4.y + GAT_EPS) * g4.y + e4.y + r4.y;
    float o2 = (acc.z * rinv + b4.z - m4.z) * rsqrtf(v4.z + GAT_EPS) * g4.z + e4.z + r4.z;
    float o3 = (acc.w * rinv + b4.w - m4.w) * rsqrtf(v4.w + GAT_EPS) * g4.w + e4.w + r4.w;
    float4 o = make_float4(o0 > 0.f ? o0 : expm1f(o0),
                           o1 > 0.f ? o1 : expm1f(o1),
                           o2 > 0.f ? o2 : expm1f(o2),
                           o3 > 0.f ? o3 : expm1f(o3));
    *(float4*)(out + (size_t)node * 128 + c) = o;
}

// ------------------------- layer-3 aggregation (online, 40ch) ---------------
__global__ void agg40(const float* __restrict__ xw, const float* __restrict__ bias,
                      float* __restrict__ out, int n) {
    int node = blockIdx.x * 8 + (threadIdx.x >> 5);
    if (node >= n) return;
    int lane = threadIdx.x & 31;
    float ed = g_ed[node];
    int s = g_off[node], e = g_off[node + 1];
    float m = -1e30f, d = 0.f, a1 = 0.f, a2 = 0.f;
    for (int i = s; i < e; i++) {
        int u = g_csr[i];
        float ev = g_es[u] + ed;
        ev = ev > 0.f ? ev : 0.2f * ev;
        float x1 = xw[(size_t)u * 40 + lane];
        float x2 = (lane < 8) ? xw[(size_t)u * 40 + 32 + lane] : 0.f;
        if (ev <= m) {
            float w = __expf(ev - m);
            d += w; a1 += w * x1; a2 += w * x2;
        } else {
            float w = __expf(m - ev);
            d = d * w + 1.f; a1 = a1 * w + x1; a2 = a2 * w + x2;
            m = ev;
        }
    }
    float inv = 1.f / d;
    out[(size_t)node * 40 + lane] = a1 * inv + bias[lane];
    if (lane < 8) out[(size_t)node * 40 + 32 + lane] = a2 * inv + bias[32 + lane];
}

// ------------------------- launch ------------------------------------------
extern "C" void kernel_launch(void* const* d_in, const int* in_sizes, int n_in,
                              void* d_out, int out_size) {
    const float* x    = (const float*)d_in[0];
    const int*   ei   = (const int*)  d_in[1];
    const float* W1   = (const float*)d_in[2];
    const float* as1  = (const float*)d_in[3];
    const float* ad1  = (const float*)d_in[4];
    const float* b1   = (const float*)d_in[5];
    const float* W2   = (const float*)d_in[6];
    const float* as2  = (const float*)d_in[7];
    const float* ad2  = (const float*)d_in[8];
    const float* b2   = (const float*)d_in[9];
    const float* W3   = (const float*)d_in[10];
    const float* as3  = (const float*)d_in[11];
    const float* ad3  = (const float*)d_in[12];
    const float* b3   = (const float*)d_in[13];
    const float* Wres = (const float*)d_in[14];
    const float* g1   = (const float*)d_in[15];
    const float* be1  = (const float*)d_in[16];
    const float* m1   = (const float*)d_in[17];
    const float* v1   = (const float*)d_in[18];
    const float* g2   = (const float*)d_in[19];
    const float* be2  = (const float*)d_in[20];
    const float* m2   = (const float*)d_in[21];
    const float* v2   = (const float*)d_in[22];

    int n = in_sizes[0] / 128;
    int E = in_sizes[1] / 2;
    const int* src = ei;
    const int* dst = ei + E;
    int tot = E + n;
    int nblk = (n + 1023) / 1024;

    float *p_xw, *p_aux, *p_h1, *p_h2;
    cudaGetSymbolAddress((void**)&p_xw,  g_xw);
    cudaGetSymbolAddress((void**)&p_aux, g_aux);
    cudaGetSymbolAddress((void**)&p_h1,  g_h1);
    cudaGetSymbolAddress((void**)&p_h2,  g_h2);

    int nb_gemm = (n + 127) / 128;
    int nb_warp = (n + 7) / 8;

    // CSR by dst (includes self loops)
    zcnt_kernel   <<<(n + 255) / 256, 256>>>(n);
    histo_kernel  <<<(tot + 255) / 256, 256>>>(dst, E, n);
    scan1_kernel  <<<nblk, 256>>>(n);
    scan2_kernel  <<<1, 32>>>(nblk, n);
    scan3_kernel  <<<(n + 255) / 256, 256>>>(n);
    scatter_kernel<<<(tot + 255) / 256, 256>>>(src, dst, E, n);

    // ---- layer 1 ----
    preB_kernel<<<64, 256>>>(W1);
    hgemm128   <<<nb_gemm, 256>>>(x, p_xw, n);
    preB_kernel<<<64, 256>>>(Wres);
    hgemm128   <<<nb_gemm, 256>>>(x, p_aux, n);
    dots128    <<<nb_warp, 256>>>(p_xw, as1, ad1, n);
    stats128   <<<nb_warp, 256>>>(n);
    aggpost128 <<<nb_warp, 256>>>(p_xw, b1, g1, be1, m1, v1, p_aux, p_h1, n);

    // ---- layer 2 ----
    preB_kernel<<<64, 256>>>(W2);
    hgemm128   <<<nb_gemm, 256>>>(p_h1, p_xw, n);
    dots128    <<<nb_warp, 256>>>(p_xw, as2, ad2, n);
    stats128   <<<nb_warp, 256>>>(n);
    aggpost128 <<<nb_warp, 256>>>(p_xw, b2, g2, be2, m2, v2, p_h1, p_h2, n);

    // ---- layer 3 ----
    gemm40<<<nb_warp, 256>>>(p_h2, W3, p_aux, n);
    dots40<<<nb_warp, 256>>>(p_aux, as3, ad3, n);
    agg40 <<<nb_warp, 256>>>(p_aux, b3, (float*)d_out, n);
}

// round 5
// speedup vs baseline: 1.5729x; 1.2643x over previous
#include <cuda_runtime.h>
#include <cuda_fp16.h>
#include <mma.h>
using namespace nvcuda;

// Problem constants
#define MAXN 50000
#define MAXE 400000
#define MAXTOT (MAXN + MAXE)
#define GAT_EPS 1e-5f

// ------------------------- scratch (device globals) ------------------------
__device__ float g_xw  [MAXN * 128];
__device__ float g_aux [MAXN * 128];
__device__ float g_h1  [MAXN * 128];
__device__ float g_h2  [MAXN * 128];
__device__ float g_es  [MAXN * 4];
__device__ float g_ed  [MAXN * 4];
__device__ int   g_cnt [MAXN];
__device__ int   g_off [MAXN + 1];
__device__ int   g_cur [MAXN];
__device__ int   g_csr [MAXTOT + 8];
__device__ int   g_bsum[64];
__device__ int   g_boff[64];
__device__ __half g_Bh[3 * 16384];
__device__ __half g_Bl[3 * 16384];

// ------------------------- CSR build ---------------------------------------
__global__ void zcnt_kernel(int n) {
    int i = blockIdx.x * blockDim.x + threadIdx.x;
    if (i < n) g_cnt[i] = 0;
}

__global__ void histo_kernel(const int* __restrict__ dst, int E, int n) {
    int i = blockIdx.x * blockDim.x + threadIdx.x;
    if (i >= E + n) return;
    int dd = (i < E) ? dst[i] : (i - E);
    atomicAdd(&g_cnt[dd], 1);
}

__global__ void scan1_kernel(int n) {
    __shared__ int wsum[8];
    int tid = threadIdx.x;
    int base = blockIdx.x * 1024 + tid * 4;
    int c0 = (base + 0 < n) ? g_cnt[base + 0] : 0;
    int c1 = (base + 1 < n) ? g_cnt[base + 1] : 0;
    int c2 = (base + 2 < n) ? g_cnt[base + 2] : 0;
    int c3 = (base + 3 < n) ? g_cnt[base + 3] : 0;
    int t = c0 + c1 + c2 + c3;
    int lane = tid & 31, wid = tid >> 5;
    int incl = t;
    #pragma unroll
    for (int o = 1; o < 32; o <<= 1) {
        int v = __shfl_up_sync(0xffffffffu, incl, o);
        if (lane >= o) incl += v;
    }
    if (lane == 31) wsum[wid] = incl;
    __syncthreads();
    if (tid == 0) {
        int r = 0;
        #pragma unroll
        for (int k = 0; k < 8; k++) { int v = wsum[k]; wsum[k] = r; r += v; }
        g_bsum[blockIdx.x] = r;
    }
    __syncthreads();
    int run = wsum[wid] + incl - t;
    if (base + 0 < n) g_off[base + 0] = run; run += c0;
    if (base + 1 < n) g_off[base + 1] = run; run += c1;
    if (base + 2 < n) g_off[base + 2] = run; run += c2;
    if (base + 3 < n) g_off[base + 3] = run;
}

__global__ void scan2_kernel(int nb, int n) {
    int lane = threadIdx.x;
    int v0 = (lane < nb) ? g_bsum[lane] : 0;
    int v1 = (32 + lane < nb) ? g_bsum[32 + lane] : 0;
    int i0 = v0;
    #pragma unroll
    for (int o = 1; o < 32; o <<= 1) {
        int q = __shfl_up_sync(0xffffffffu, i0, o);
        if (lane >= o) i0 += q;
    }
    int tot0 = __shfl_sync(0xffffffffu, i0, 31);
    int i1 = v1;
    #pragma unroll
    for (int o = 1; o < 32; o <<= 1) {
        int q = __shfl_up_sync(0xffffffffu, i1, o);
        if (lane >= o) i1 += q;
    }
    i1 += tot0;
    if (lane < nb) g_boff[lane] = i0 - v0;
    if (32 + lane < nb) g_boff[32 + lane] = i1 - v1;
    int grand = __shfl_sync(0xffffffffu, i1, 31);
    if (lane == 0) g_off[n] = grand;
}

__global__ void scan3_kernel(int n) {
    int i = blockIdx.x * blockDim.x + threadIdx.x;
    if (i >= n) return;
    int o = g_off[i] + g_boff[i >> 10];
    g_off[i] = o;
    g_cur[i] = o;
}

__global__ void scatter_kernel(const int* __restrict__ src, const int* __restrict__ dst,
                               int E, int n) {
    int i = blockIdx.x * blockDim.x + threadIdx.x;
    if (i >= E + n) return;
    int ss, dd;
    if (i < E) { ss = src[i]; dd = dst[i]; }
    else       { ss = dd = i - E; }
    int p = atomicAdd(&g_cur[dd], 1);
    g_csr[p] = ss;
}

// ------------------------- B preconversion: W1, Wres, W2 in one launch ------
__global__ void preB_all(const float* __restrict__ W1, const float* __restrict__ Wres,
                         const float* __restrict__ W2) {
    int i = blockIdx.x * blockDim.x + threadIdx.x;
    if (i >= 3 * 16384) return;
    const float* W = (i < 16384) ? W1 : (i < 32768 ? Wres : W2);
    float v = W[i & 16383];
    __half h = __float2half_rn(v);
    g_Bh[i] = h;
    g_Bl[i] = __float2half_rn(v - __half2float(h));
}

// ------------------------- WMMA fp16x3 GEMM + fused dots --------------------
// C[M,128] = A[M,128] @ B[128,128]; if a_s != null, also es/ed per head.
#define LDP 136                                  // padded smem stride (halves)
#define HG_SMEM (4 * 128 * LDP * 2)              // 139264 bytes

__global__ void __launch_bounds__(256)
hgemm128(const float* __restrict__ A, float* __restrict__ C, int M, int boff,
         const float* __restrict__ a_s, const float* __restrict__ a_d) {
    extern __shared__ __half sm[];
    __half* sAh = sm;
    __half* sAl = sAh + 128 * LDP;
    __half* sBh = sAl + 128 * LDP;
    __half* sBl = sBh + 128 * LDP;
    int tid = threadIdx.x;
    int wid = tid >> 5, lane = tid & 31;
    int wm = wid & 3, wn = wid >> 2;
    int row0 = blockIdx.x * 128;

    // load + convert A [128 x 128] (float2 -> half2)
    #pragma unroll 8
    for (int it = 0; it < 32; it++) {
        int idx = tid + it * 256;            // 8192 pairs
        int r = idx >> 6, c2 = idx & 63;
        int gr = row0 + r;
        float2 v = make_float2(0.f, 0.f);
        if (gr < M) v = *(const float2*)(A + (size_t)gr * 128 + c2 * 2);
        __half hx = __float2half_rn(v.x), hy = __float2half_rn(v.y);
        *(__half2*)(sAh + r * LDP + c2 * 2) = __halves2half2(hx, hy);
        *(__half2*)(sAl + r * LDP + c2 * 2) =
            __halves2half2(__float2half_rn(v.x - __half2float(hx)),
                           __float2half_rn(v.y - __half2float(hy)));
    }
    // load preconverted B halves
    {
        const __half2* bh = (const __half2*)(g_Bh + boff);
        const __half2* bl = (const __half2*)(g_Bl + boff);
        #pragma unroll 8
        for (int it = 0; it < 32; it++) {
            int idx = tid + it * 256;
            int r = idx >> 6, c2 = idx & 63;
            *(__half2*)(sBh + r * LDP + c2 * 2) = bh[idx];
            *(__half2*)(sBl + r * LDP + c2 * 2) = bl[idx];
        }
    }
    __syncthreads();

    wmma::fragment<wmma::accumulator, 16, 16, 16, float> acc[2][4];
    #pragma unroll
    for (int i = 0; i < 2; i++)
        #pragma unroll
        for (int j = 0; j < 4; j++)
            wmma::fill_fragment(acc[i][j], 0.f);

    #pragma unroll
    for (int kk = 0; kk < 8; kk++) {
        wmma::fragment<wmma::matrix_a, 16, 16, 16, __half, wmma::row_major> ah[2], al[2];
        #pragma unroll
        for (int i = 0; i < 2; i++) {
            wmma::load_matrix_sync(ah[i], sAh + (wm * 32 + i * 16) * LDP + kk * 16, LDP);
            wmma::load_matrix_sync(al[i], sAl + (wm * 32 + i * 16) * LDP + kk * 16, LDP);
        }
        #pragma unroll
        for (int j = 0; j < 4; j++) {
            wmma::fragment<wmma::matrix_b, 16, 16, 16, __half, wmma::row_major> bh, bl;
            wmma::load_matrix_sync(bh, sBh + kk * 16 * LDP + wn * 64 + j * 16, LDP);
            wmma::load_matrix_sync(bl, sBl + kk * 16 * LDP + wn * 64 + j * 16, LDP);
            #pragma unroll
            for (int i = 0; i < 2; i++) {
                wmma::mma_sync(acc[i][j], ah[i], bh, acc[i][j]);
                wmma::mma_sync(acc[i][j], al[i], bh, acc[i][j]);
                wmma::mma_sync(acc[i][j], ah[i], bl, acc[i][j]);
            }
        }
    }

    #pragma unroll
    for (int i = 0; i < 2; i++) {
        int gr = row0 + wm * 32 + i * 16;
        if (gr < M) {
            #pragma unroll
            for (int j = 0; j < 4; j++)
                wmma::store_matrix_sync(C + (size_t)gr * 128 + wn * 64 + j * 16,
                                        acc[i][j], 128, wmma::mem_row_major);
        }
    }

    // fused dots: es/ed per head (reads freshly stored C; intra-block visibility)
    if (a_s) {
        __syncthreads();
        float4 asv = *(const float4*)(a_s + lane * 4);
        float4 adv = *(const float4*)(a_d + lane * 4);
        #pragma unroll
        for (int rr = 0; rr < 16; rr++) {
            int row = row0 + wid * 16 + rr;
            if (row >= M) break;
            float4 xv = *(const float4*)(C + (size_t)row * 128 + lane * 4);
            float ps = xv.x * asv.x + xv.y * asv.y + xv.z * asv.z + xv.w * asv.w;
            float pd = xv.x * adv.x + xv.y * adv.y + xv.z * adv.z + xv.w * adv.w;
            ps += __shfl_xor_sync(0xffffffffu, ps, 1);
            ps += __shfl_xor_sync(0xffffffffu, ps, 2);
            ps += __shfl_xor_sync(0xffffffffu, ps, 4);
            pd += __shfl_xor_sync(0xffffffffu, pd, 1);
            pd += __shfl_xor_sync(0xffffffffu, pd, 2);
            pd += __shfl_xor_sync(0xffffffffu, pd, 4);
            if ((lane & 7) == 0) {
                int h = lane >> 3;
                g_es[row * 4 + h] = ps;
                g_ed[row * 4 + h] = pd;
            }
        }
    }
}

// ------------------------- layer-3 GEMM (40 cols) + fused dots --------------
__global__ void gemm40(const float* __restrict__ A, const float* __restrict__ B,
                       const float* __restrict__ a_s, const float* __restrict__ a_d,
                       float* __restrict__ C, int M) {
    __shared__ float Ws[128 * 40];
    for (int i = threadIdx.x; i < 128 * 40; i += blockDim.x) Ws[i] = B[i];
    __syncthreads();
    int row  = blockIdx.x * 8 + (threadIdx.x >> 5);
    int lane = threadIdx.x & 31;
    if (row >= M) return;
    const float* a = A + (size_t)row * 128;
    float acc1 = 0.f, acc2 = 0.f;
    #pragma unroll 8
    for (int k = 0; k < 128; k++) {
        float av = __ldg(a + k);
        acc1 += av * Ws[k * 40 + lane];
        if (lane < 8) acc2 += av * Ws[k * 40 + 32 + lane];
    }
    C[(size_t)row * 40 + lane] = acc1;
    if (lane < 8) C[(size_t)row * 40 + 32 + lane] = acc2;
    // fused dots (single head, 40 channels) straight from accumulators
    float ps = acc1 * a_s[lane] + ((lane < 8) ? acc2 * a_s[32 + lane] : 0.f);
    float pd = acc1 * a_d[lane] + ((lane < 8) ? acc2 * a_d[32 + lane] : 0.f);
    #pragma unroll
    for (int o = 16; o; o >>= 1) {
        ps += __shfl_xor_sync(0xffffffffu, ps, o);
        pd += __shfl_xor_sync(0xffffffffu, pd, o);
    }
    if (lane == 0) { g_es[row] = ps; g_ed[row] = pd; }
}

// ------------------------- fused GAT agg: stats + gather + BN/res/ELU -------
// warp per node. Pass 1: lanes (head=lane>>3, esub=lane&7) compute softmax
// stats branch-free. Pass 2: weighted gather + epilogue.
__global__ void agg128(const float* __restrict__ xw,
                       const float* __restrict__ bias,
                       const float* __restrict__ gam, const float* __restrict__ bet,
                       const float* __restrict__ mean, const float* __restrict__ var,
                       const float* __restrict__ res, float* __restrict__ out, int n) {
    int node = blockIdx.x * 8 + (threadIdx.x >> 5);
    if (node >= n) return;
    int lane = threadIdx.x & 31;
    int head = lane >> 3, esub = lane & 7;
    float ed = g_ed[node * 4 + head];
    int s = g_off[node], e = g_off[node + 1];

    // pass 1: max + denominator (online over 8-edge chunks, branch-free)
    float m = -1e30f, den = 0.f;
    for (int base = s; base < e; base += 8) {
        int i = base + esub;
        bool val = i < e;
        int u = val ? g_csr[i] : 0;
        float ev = g_es[u * 4 + head] + ed;
        ev = ev > 0.f ? ev : 0.2f * ev;
        if (!val) ev = -1e30f;
        float gm = ev;
        gm = fmaxf(gm, __shfl_xor_sync(0xffffffffu, gm, 1));
        gm = fmaxf(gm, __shfl_xor_sync(0xffffffffu, gm, 2));
        gm = fmaxf(gm, __shfl_xor_sync(0xffffffffu, gm, 4));
        float nm = fmaxf(m, gm);
        float w = __expf(ev - nm);
        w += __shfl_xor_sync(0xffffffffu, w, 1);
        w += __shfl_xor_sync(0xffffffffu, w, 2);
        w += __shfl_xor_sync(0xffffffffu, w, 4);
        den = den * __expf(m - nm) + w;
        m = nm;
    }
    float rinv = 1.f / den;

    // pass 2: weighted gather (all lanes iterate edges; L2-hot es re-gather)
    float4 acc = make_float4(0.f, 0.f, 0.f, 0.f);
    int u = g_csr[s];
    for (int i = s; i < e; i++) {
        int un = g_csr[i + 1];                    // padded: safe overread
        float ev = g_es[u * 4 + head] + ed;
        ev = ev > 0.f ? ev : 0.2f * ev;
        float w = __expf(ev - m);
        float4 xv = *(const float4*)(xw + (size_t)u * 128 + lane * 4);
        acc.x += w * xv.x; acc.y += w * xv.y;
        acc.z += w * xv.z; acc.w += w * xv.w;
        u = un;
    }

    int c = lane * 4;
    float4 b4 = *(const float4*)(bias + c);
    float4 g4 = *(const float4*)(gam + c);
    float4 e4 = *(const float4*)(bet + c);
    float4 m4 = *(const float4*)(mean + c);
    float4 v4 = *(const float4*)(var + c);
    float4 r4 = *(const float4*)(res + (size_t)node * 128 + c);
    float o0 = (acc.x * rinv + b4.x - m4.x) * rsqrtf(v4.x + GAT_EPS) * g4.x + e4.x + r4.x;
    float o1 = (acc.y * rinv + b4.y - m4.y) * rsqrtf(v4.y + GAT_EPS) * g4.y + e4.y + r4.y;
    float o2 = (acc.z * rinv + b4.z - m4.z) * rsqrtf(v4.z + GAT_EPS) * g4.z + e4.z + r4.z;
    float o3 = (acc.w * rinv + b4.w - m4.w) * rsqrtf(v4.w + GAT_EPS) * g4.w + e4.w + r4.w;
    float4 o = make_float4(o0 > 0.f ? o0 : expm1f(o0),
                           o1 > 0.f ? o1 : expm1f(o1),
                           o2 > 0.f ? o2 : expm1f(o2),
                           o3 > 0.f ? o3 : expm1f(o3));
    *(float4*)(out + (size_t)node * 128 + c) = o;
}

// ------------------------- layer-3 agg (two-pass, branch-free) --------------
__global__ void agg40(const float* __restrict__ xw, const float* __restrict__ bias,
                      float* __restrict__ out, int n) {
    int node = blockIdx.x * 8 + (threadIdx.x >> 5);
    if (node >= n) return;
    int lane = threadIdx.x & 31;
    float ed = g_ed[node];
    int s = g_off[node], e = g_off[node + 1];

    float m = -1e30f, den = 0.f;
    for (int base = s; base < e; base += 32) {
        int i = base + lane;
        bool val = i < e;
        int u = val ? g_csr[i] : 0;
        float ev = g_es[u] + ed;
        ev = ev > 0.f ? ev : 0.2f * ev;
        if (!val) ev = -1e30f;
        float gm = ev;
        #pragma unroll
        for (int o = 16; o; o >>= 1) gm = fmaxf(gm, __shfl_xor_sync(0xffffffffu, gm, o));
        float nm = fmaxf(m, gm);
        float w = __expf(ev - nm);
        #pragma unroll
        for (int o = 16; o; o >>= 1) w += __shfl_xor_sync(0xffffffffu, w, o);
        den = den * __expf(m - nm) + w;
        m = nm;
    }
    float rinv = 1.f / den;

    float a1 = 0.f, a2 = 0.f;
    int u = g_csr[s];
    for (int i = s; i < e; i++) {
        int un = g_csr[i + 1];
        float ev = g_es[u] + ed;
        ev = ev > 0.f ? ev : 0.2f * ev;
        float w = __expf(ev - m);
        a1 += w * xw[(size_t)u * 40 + lane];
        if (lane < 8) a2 += w * xw[(size_t)u * 40 + 32 + lane];
        u = un;
    }
    out[(size_t)node * 40 + lane] = a1 * rinv + bias[lane];
    if (lane < 8) out[(size_t)node * 40 + 32 + lane] = a2 * rinv + bias[32 + lane];
}

// ------------------------- launch ------------------------------------------
extern "C" void kernel_launch(void* const* d_in, const int* in_sizes, int n_in,
                              void* d_out, int out_size) {
    const float* x    = (const float*)d_in[0];
    const int*   ei   = (const int*)  d_in[1];
    const float* W1   = (const float*)d_in[2];
    const float* as1  = (const float*)d_in[3];
    const float* ad1  = (const float*)d_in[4];
    const float* b1   = (const float*)d_in[5];
    const float* W2   = (const float*)d_in[6];
    const float* as2  = (const float*)d_in[7];
    const float* ad2  = (const float*)d_in[8];
    const float* b2   = (const float*)d_in[9];
    const float* W3   = (const float*)d_in[10];
    const float* as3  = (const float*)d_in[11];
    const float* ad3  = (const float*)d_in[12];
    const float* b3   = (const float*)d_in[13];
    const float* Wres = (const float*)d_in[14];
    const float* g1   = (const float*)d_in[15];
    const float* be1  = (const float*)d_in[16];
    const float* m1   = (const float*)d_in[17];
    const float* v1   = (const float*)d_in[18];
    const float* g2   = (const float*)d_in[19];
    const float* be2  = (const float*)d_in[20];
    const float* m2   = (const float*)d_in[21];
    const float* v2   = (const float*)d_in[22];

    int n = in_sizes[0] / 128;
    int E = in_sizes[1] / 2;
    const int* src = ei;
    const int* dst = ei + E;
    int tot = E + n;
    int nblk = (n + 1023) / 1024;

    float *p_xw, *p_aux, *p_h1, *p_h2;
    cudaGetSymbolAddress((void**)&p_xw,  g_xw);
    cudaGetSymbolAddress((void**)&p_aux, g_aux);
    cudaGetSymbolAddress((void**)&p_h1,  g_h1);
    cudaGetSymbolAddress((void**)&p_h2,  g_h2);

    cudaFuncSetAttribute(hgemm128, cudaFuncAttributeMaxDynamicSharedMemorySize, HG_SMEM);

    int nb_gemm = (n + 127) / 128;
    int nb_warp = (n + 7) / 8;

    // CSR by dst (includes self loops)
    zcnt_kernel   <<<(n + 255) / 256, 256>>>(n);
    histo_kernel  <<<(tot + 255) / 256, 256>>>(dst, E, n);
    scan1_kernel  <<<nblk, 256>>>(n);
    scan2_kernel  <<<1, 32>>>(nblk, n);
    scan3_kernel  <<<(n + 255) / 256, 256>>>(n);
    scatter_kernel<<<(tot + 255) / 256, 256>>>(src, dst, E, n);

    // all weight conversions in one launch
    preB_all<<<192, 256>>>(W1, Wres, W2);

    // ---- layer 1 ----
    hgemm128<<<nb_gemm, 256, HG_SMEM>>>(x, p_xw, n, 0, as1, ad1);
    hgemm128<<<nb_gemm, 256, HG_SMEM>>>(x, p_aux, n, 16384, nullptr, nullptr);
    agg128  <<<nb_warp, 256>>>(p_xw, b1, g1, be1, m1, v1, p_aux, p_h1, n);

    // ---- layer 2 ----
    hgemm128<<<nb_gemm, 256, HG_SMEM>>>(p_h1, p_xw, n, 32768, as2, ad2);
    agg128  <<<nb_warp, 256>>>(p_xw, b2, g2, be2, m2, v2, p_h1, p_h2, n);

    // ---- layer 3 ----
    gemm40<<<nb_warp, 256>>>(p_h2, W3, as3, ad3, p_aux, n);
    agg40 <<<nb_warp, 256>>>(p_aux, b3, (float*)d_out, n);
}

// round 6
// speedup vs baseline: 1.6696x; 1.0615x over previous
#include <cuda_runtime.h>
#include <cuda_fp16.h>
#include <mma.h>
using namespace nvcuda;

// Problem constants
#define MAXN 50000
#define MAXE 400000
#define MAXTOT (MAXN + MAXE)
#define GAT_EPS 1e-5f

// ------------------------- scratch (device globals) ------------------------
__device__ float g_xw  [MAXN * 128];
__device__ float g_aux [MAXN * 128];
__device__ float g_h1  [MAXN * 128];
__device__ float g_h2  [MAXN * 128];
__device__ float g_es  [MAXN * 4];
__device__ float g_ed  [MAXN * 4];
__device__ int   g_cnt [MAXN];
__device__ int   g_off [MAXN + 1];
__device__ int   g_cur [MAXN];
__device__ int   g_csr [MAXTOT + 8];
__device__ int   g_bsum[64];
__device__ int   g_boff[64];
__device__ __half g_Bh[3 * 16384];
__device__ __half g_Bl[3 * 16384];

// ------------------------- preB (+ fused zcnt) ------------------------------
__global__ void preB_zcnt(const float* __restrict__ W1, const float* __restrict__ Wres,
                          const float* __restrict__ W2, int n) {
    int i = blockIdx.x * blockDim.x + threadIdx.x;
    if (i < n) g_cnt[i] = 0;
    if (i >= 3 * 16384) return;
    const float* W = (i < 16384) ? W1 : (i < 32768 ? Wres : W2);
    float v = W[i & 16383];
    __half h = __float2half_rn(v);
    g_Bh[i] = h;
    g_Bl[i] = __float2half_rn(v - __half2float(h));
}

__global__ void histo_kernel(const int* __restrict__ dst, int E, int n) {
    int i = blockIdx.x * blockDim.x + threadIdx.x;
    if (i >= E + n) return;
    int dd = (i < E) ? dst[i] : (i - E);
    atomicAdd(&g_cnt[dd], 1);
}

__global__ void scan1_kernel(int n) {
    __shared__ int wsum[8];
    int tid = threadIdx.x;
    int base = blockIdx.x * 1024 + tid * 4;
    int c0 = (base + 0 < n) ? g_cnt[base + 0] : 0;
    int c1 = (base + 1 < n) ? g_cnt[base + 1] : 0;
    int c2 = (base + 2 < n) ? g_cnt[base + 2] : 0;
    int c3 = (base + 3 < n) ? g_cnt[base + 3] : 0;
    int t = c0 + c1 + c2 + c3;
    int lane = tid & 31, wid = tid >> 5;
    int incl = t;
    #pragma unroll
    for (int o = 1; o < 32; o <<= 1) {
        int v = __shfl_up_sync(0xffffffffu, incl, o);
        if (lane >= o) incl += v;
    }
    if (lane == 31) wsum[wid] = incl;
    __syncthreads();
    if (tid == 0) {
        int r = 0;
        #pragma unroll
        for (int k = 0; k < 8; k++) { int v = wsum[k]; wsum[k] = r; r += v; }
        g_bsum[blockIdx.x] = r;
    }
    __syncthreads();
    int run = wsum[wid] + incl - t;
    if (base + 0 < n) g_off[base + 0] = run; run += c0;
    if (base + 1 < n) g_off[base + 1] = run; run += c1;
    if (base + 2 < n) g_off[base + 2] = run; run += c2;
    if (base + 3 < n) g_off[base + 3] = run;
}

__global__ void scan2_kernel(int nb, int n) {
    int lane = threadIdx.x;
    int v0 = (lane < nb) ? g_bsum[lane] : 0;
    int v1 = (32 + lane < nb) ? g_bsum[32 + lane] : 0;
    int i0 = v0;
    #pragma unroll
    for (int o = 1; o < 32; o <<= 1) {
        int q = __shfl_up_sync(0xffffffffu, i0, o);
        if (lane >= o) i0 += q;
    }
    int tot0 = __shfl_sync(0xffffffffu, i0, 31);
    int i1 = v1;
    #pragma unroll
    for (int o = 1; o < 32; o <<= 1) {
        int q = __shfl_up_sync(0xffffffffu, i1, o);
        if (lane >= o) i1 += q;
    }
    i1 += tot0;
    if (lane < nb) g_boff[lane] = i0 - v0;
    if (32 + lane < nb) g_boff[32 + lane] = i1 - v1;
    int grand = __shfl_sync(0xffffffffu, i1, 31);
    if (lane == 0) g_off[n] = grand;
}

__global__ void scan3_kernel(int n) {
    int i = blockIdx.x * blockDim.x + threadIdx.x;
    if (i >= n) return;
    int o = g_off[i] + g_boff[i >> 10];
    g_off[i] = o;
    g_cur[i] = o;
}

__global__ void scatter_kernel(const int* __restrict__ src, const int* __restrict__ dst,
                               int E, int n) {
    int i = blockIdx.x * blockDim.x + threadIdx.x;
    if (i >= E + n) return;
    int ss, dd;
    if (i < E) { ss = src[i]; dd = dst[i]; }
    else       { ss = dd = i - E; }
    int p = atomicAdd(&g_cur[dd], 1);
    g_csr[p] = ss;
}

// ------------------------- WMMA fp16x3 GEMM + fused dots --------------------
// K chunked by 64: SMEM 71.7KB -> 2 CTAs/SM (16 warps resident).
#define LDA 72                                   // half stride, A tiles
#define LDB 136                                  // half stride, B tiles
#define HG_SMEM ((2 * 128 * LDA + 2 * 64 * LDB) * 2)   // 71680 bytes

__global__ void __launch_bounds__(256, 2)
hgemm128(const float* __restrict__ A, float* __restrict__ C, int M, int boff,
         const float* __restrict__ a_s, const float* __restrict__ a_d) {
    extern __shared__ __half sm[];
    __half* sAh = sm;
    __half* sAl = sAh + 128 * LDA;
    __half* sBh = sAl + 128 * LDA;
    __half* sBl = sBh + 64 * LDB;
    int tid = threadIdx.x;
    int wid = tid >> 5, lane = tid & 31;
    int wm = wid & 3, wn = wid >> 2;
    int row0 = blockIdx.x * 128;

    wmma::fragment<wmma::accumulator, 16, 16, 16, float> acc[2][4];
    #pragma unroll
    for (int i = 0; i < 2; i++)
        #pragma unroll
        for (int j = 0; j < 4; j++)
            wmma::fill_fragment(acc[i][j], 0.f);

    #pragma unroll
    for (int kc = 0; kc < 2; kc++) {
        // A chunk [128 x 64] fp32 -> hi/lo half2
        #pragma unroll
        for (int it = 0; it < 16; it++) {
            int idx = tid + it * 256;            // 4096 pairs
            int r = idx >> 5, c2 = idx & 31;
            int gr = row0 + r;
            float2 v = make_float2(0.f, 0.f);
            if (gr < M) v = *(const float2*)(A + (size_t)gr * 128 + kc * 64 + c2 * 2);
            __half hx = __float2half_rn(v.x), hy = __float2half_rn(v.y);
            *(__half2*)(sAh + r * LDA + c2 * 2) = __halves2half2(hx, hy);
            *(__half2*)(sAl + r * LDA + c2 * 2) =
                __halves2half2(__float2half_rn(v.x - __half2float(hx)),
                               __float2half_rn(v.y - __half2float(hy)));
        }
        // B chunk [64 x 128] from preconverted halves
        {
            const __half2* bh = (const __half2*)(g_Bh + boff + kc * 64 * 128);
            const __half2* bl = (const __half2*)(g_Bl + boff + kc * 64 * 128);
            #pragma unroll
            for (int it = 0; it < 16; it++) {
                int idx = tid + it * 256;        // 4096 pairs
                int r = idx >> 6, c2 = idx & 63;
                *(__half2*)(sBh + r * LDB + c2 * 2) = bh[idx];
                *(__half2*)(sBl + r * LDB + c2 * 2) = bl[idx];
            }
        }
        __syncthreads();

        #pragma unroll
        for (int kk = 0; kk < 4; kk++) {
            wmma::fragment<wmma::matrix_a, 16, 16, 16, __half, wmma::row_major> ah[2], al[2];
            #pragma unroll
            for (int i = 0; i < 2; i++) {
                wmma::load_matrix_sync(ah[i], sAh + (wm * 32 + i * 16) * LDA + kk * 16, LDA);
                wmma::load_matrix_sync(al[i], sAl + (wm * 32 + i * 16) * LDA + kk * 16, LDA);
            }
            #pragma unroll
            for (int j = 0; j < 4; j++) {
                wmma::fragment<wmma::matrix_b, 16, 16, 16, __half, wmma::row_major> bh, bl;
                wmma::load_matrix_sync(bh, sBh + kk * 16 * LDB + wn * 64 + j * 16, LDB);
                wmma::load_matrix_sync(bl, sBl + kk * 16 * LDB + wn * 64 + j * 16, LDB);
                #pragma unroll
                for (int i = 0; i < 2; i++) {
                    wmma::mma_sync(acc[i][j], ah[i], bh, acc[i][j]);
                    wmma::mma_sync(acc[i][j], al[i], bh, acc[i][j]);
                    wmma::mma_sync(acc[i][j], ah[i], bl, acc[i][j]);
                }
            }
        }
        __syncthreads();
    }

    #pragma unroll
    for (int i = 0; i < 2; i++) {
        int gr = row0 + wm * 32 + i * 16;
        if (gr < M) {
            #pragma unroll
            for (int j = 0; j < 4; j++)
                wmma::store_matrix_sync(C + (size_t)gr * 128 + wn * 64 + j * 16,
                                        acc[i][j], 128, wmma::mem_row_major);
        }
    }

    // fused dots: es/ed per head (reads freshly stored C; intra-block visibility)
    if (a_s) {
        __syncthreads();
        float4 asv = *(const float4*)(a_s + lane * 4);
        float4 adv = *(const float4*)(a_d + lane * 4);
        #pragma unroll
        for (int rr = 0; rr < 16; rr++) {
            int row = row0 + wid * 16 + rr;
            if (row >= M) break;
            float4 xv = *(const float4*)(C + (size_t)row * 128 + lane * 4);
            float ps = xv.x * asv.x + xv.y * asv.y + xv.z * asv.z + xv.w * asv.w;
            float pd = xv.x * adv.x + xv.y * adv.y + xv.z * adv.z + xv.w * adv.w;
            ps += __shfl_xor_sync(0xffffffffu, ps, 1);
            ps += __shfl_xor_sync(0xffffffffu, ps, 2);
            ps += __shfl_xor_sync(0xffffffffu, ps, 4);
            pd += __shfl_xor_sync(0xffffffffu, pd, 1);
            pd += __shfl_xor_sync(0xffffffffu, pd, 2);
            pd += __shfl_xor_sync(0xffffffffu, pd, 4);
            if ((lane & 7) == 0) {
                int h = lane >> 3;
                g_es[row * 4 + h] = ps;
                g_ed[row * 4 + h] = pd;
            }
        }
    }
}

// ------------------------- layer-3 GEMM (40 cols) + fused dots --------------
__global__ void gemm40(const float* __restrict__ A, const float* __restrict__ B,
                       const float* __restrict__ a_s, const float* __restrict__ a_d,
                       float* __restrict__ C, int M) {
    __shared__ float Ws[128 * 40];
    for (int i = threadIdx.x; i < 128 * 40; i += blockDim.x) Ws[i] = B[i];
    __syncthreads();
    int row  = blockIdx.x * 8 + (threadIdx.x >> 5);
    int lane = threadIdx.x & 31;
    if (row >= M) return;
    const float* a = A + (size_t)row * 128;
    float acc1 = 0.f, acc2 = 0.f;
    #pragma unroll 8
    for (int k = 0; k < 128; k++) {
        float av = __ldg(a + k);
        acc1 += av * Ws[k * 40 + lane];
        if (lane < 8) acc2 += av * Ws[k * 40 + 32 + lane];
    }
    C[(size_t)row * 40 + lane] = acc1;
    if (lane < 8) C[(size_t)row * 40 + 32 + lane] = acc2;
    float ps = acc1 * a_s[lane] + ((lane < 8) ? acc2 * a_s[32 + lane] : 0.f);
    float pd = acc1 * a_d[lane] + ((lane < 8) ? acc2 * a_d[32 + lane] : 0.f);
    #pragma unroll
    for (int o = 16; o; o >>= 1) {
        ps += __shfl_xor_sync(0xffffffffu, ps, o);
        pd += __shfl_xor_sync(0xffffffffu, pd, o);
    }
    if (lane == 0) { g_es[row] = ps; g_ed[row] = pd; }
}

// ------------------------- fused GAT agg: stats + gather + BN/res/ELU -------
__global__ void agg128(const float* __restrict__ xw,
                       const float* __restrict__ bias,
                       const float* __restrict__ gam, const float* __restrict__ bet,
                       const float* __restrict__ mean, const float* __restrict__ var,
                       const float* __restrict__ res, float* __restrict__ out, int n) {
    int node = blockIdx.x * 8 + (threadIdx.x >> 5);
    if (node >= n) return;
    int lane = threadIdx.x & 31;
    int head = lane >> 3, esub = lane & 7;
    float ed = g_ed[node * 4 + head];
    int s = g_off[node], e = g_off[node + 1];

    float m = -1e30f, den = 0.f;
    for (int base = s; base < e; base += 8) {
        int i = base + esub;
        bool val = i < e;
        int u = val ? g_csr[i] : 0;
        float ev = g_es[u * 4 + head] + ed;
        ev = ev > 0.f ? ev : 0.2f * ev;
        if (!val) ev = -1e30f;
        float gm = ev;
        gm = fmaxf(gm, __shfl_xor_sync(0xffffffffu, gm, 1));
        gm = fmaxf(gm, __shfl_xor_sync(0xffffffffu, gm, 2));
        gm = fmaxf(gm, __shfl_xor_sync(0xffffffffu, gm, 4));
        float nm = fmaxf(m, gm);
        float w = __expf(ev - nm);
        w += __shfl_xor_sync(0xffffffffu, w, 1);
        w += __shfl_xor_sync(0xffffffffu, w, 2);
        w += __shfl_xor_sync(0xffffffffu, w, 4);
        den = den * __expf(m - nm) + w;
        m = nm;
    }
    float rinv = 1.f / den;

    float4 acc = make_float4(0.f, 0.f, 0.f, 0.f);
    int u = g_csr[s];
    for (int i = s; i < e; i++) {
        int un = g_csr[i + 1];
        float ev = g_es[u * 4 + head] + ed;
        ev = ev > 0.f ? ev : 0.2f * ev;
        float w = __expf(ev - m);
        float4 xv = *(const float4*)(xw + (size_t)u * 128 + lane * 4);
        acc.x += w * xv.x; acc.y += w * xv.y;
        acc.z += w * xv.z; acc.w += w * xv.w;
        u = un;
    }

    int c = lane * 4;
    float4 b4 = *(const float4*)(bias + c);
    float4 g4 = *(const float4*)(gam + c);
    float4 e4 = *(const float4*)(bet + c);
    float4 m4 = *(const float4*)(mean + c);
    float4 v4 = *(const float4*)(var + c);
    float4 r4 = *(const float4*)(res + (size_t)node * 128 + c);
    float o0 = (acc.x * rinv + b4.x - m4.x) * rsqrtf(v4.x + GAT_EPS) * g4.x + e4.x + r4.x;
    float o1 = (acc.y * rinv + b4.y - m4.y) * rsqrtf(v4.y + GAT_EPS) * g4.y + e4.y + r4.y;
    float o2 = (acc.z * rinv + b4.z - m4.z) * rsqrtf(v4.z + GAT_EPS) * g4.z + e4.z + r4.z;
    float o3 = (acc.w * rinv + b4.w - m4.w) * rsqrtf(v4.w + GAT_EPS) * g4.w + e4.w + r4.w;
    float4 o = make_float4(o0 > 0.f ? o0 : expm1f(o0),
                           o1 > 0.f ? o1 : expm1f(o1),
                           o2 > 0.f ? o2 : expm1f(o2),
                           o3 > 0.f ? o3 : expm1f(o3));
    *(float4*)(out + (size_t)node * 128 + c) = o;
}

// ------------------------- layer-3 agg (two-pass, branch-free) --------------
__global__ void agg40(const float* __restrict__ xw, const float* __restrict__ bias,
                      float* __restrict__ out, int n) {
    int node = blockIdx.x * 8 + (threadIdx.x >> 5);
    if (node >= n) return;
    int lane = threadIdx.x & 31;
    float ed = g_ed[node];
    int s = g_off[node], e = g_off[node + 1];

    float m = -1e30f, den = 0.f;
    for (int base = s; base < e; base += 32) {
        int i = base + lane;
        bool val = i < e;
        int u = val ? g_csr[i] : 0;
        float ev = g_es[u] + ed;
        ev = ev > 0.f ? ev : 0.2f * ev;
        if (!val) ev = -1e30f;
        float gm = ev;
        #pragma unroll
        for (int o = 16; o; o >>= 1) gm = fmaxf(gm, __shfl_xor_sync(0xffffffffu, gm, o));
        float nm = fmaxf(m, gm);
        float w = __expf(ev - nm);
        #pragma unroll
        for (int o = 16; o; o >>= 1) w += __shfl_xor_sync(0xffffffffu, w, o);
        den = den * __expf(m - nm) + w;
        m = nm;
    }
    float rinv = 1.f / den;

    float a1 = 0.f, a2 = 0.f;
    int u = g_csr[s];
    for (int i = s; i < e; i++) {
        int un = g_csr[i + 1];
        float ev = g_es[u] + ed;
        ev = ev > 0.f ? ev : 0.2f * ev;
        float w = __expf(ev - m);
        a1 += w * xw[(size_t)u * 40 + lane];
        if (lane < 8) a2 += w * xw[(size_t)u * 40 + 32 + lane];
        u = un;
    }
    out[(size_t)node * 40 + lane] = a1 * rinv + bias[lane];
    if (lane < 8) out[(size_t)node * 40 + 32 + lane] = a2 * rinv + bias[32 + lane];
}

// ------------------------- launch ------------------------------------------
extern "C" void kernel_launch(void* const* d_in, const int* in_sizes, int n_in,
                              void* d_out, int out_size) {
    const float* x    = (const float*)d_in[0];
    const int*   ei   = (const int*)  d_in[1];
    const float* W1   = (const float*)d_in[2];
    const float* as1  = (const float*)d_in[3];
    const float* ad1  = (const float*)d_in[4];
    const float* b1   = (const float*)d_in[5];
    const float* W2   = (const float*)d_in[6];
    const float* as2  = (const float*)d_in[7];
    const float* ad2  = (const float*)d_in[8];
    const float* b2   = (const float*)d_in[9];
    const float* W3   = (const float*)d_in[10];
    const float* as3  = (const float*)d_in[11];
    const float* ad3  = (const float*)d_in[12];
    const float* b3   = (const float*)d_in[13];
    const float* Wres = (const float*)d_in[14];
    const float* g1   = (const float*)d_in[15];
    const float* be1  = (const float*)d_in[16];
    const float* m1   = (const float*)d_in[17];
    const float* v1   = (const float*)d_in[18];
    const float* g2   = (const float*)d_in[19];
    const float* be2  = (const float*)d_in[20];
    const float* m2   = (const float*)d_in[21];
    const float* v2   = (const float*)d_in[22];

    int n = in_sizes[0] / 128;
    int E = in_sizes[1] / 2;
    const int* src = ei;
    const int* dst = ei + E;
    int tot = E + n;
    int nblk = (n + 1023) / 1024;

    float *p_xw, *p_aux, *p_h1, *p_h2;
    cudaGetSymbolAddress((void**)&p_xw,  g_xw);
    cudaGetSymbolAddress((void**)&p_aux, g_aux);
    cudaGetSymbolAddress((void**)&p_h1,  g_h1);
    cudaGetSymbolAddress((void**)&p_h2,  g_h2);

    cudaFuncSetAttribute(hgemm128, cudaFuncAttributeMaxDynamicSharedMemorySize, HG_SMEM);

    int nb_gemm = (n + 127) / 128;
    int nb_warp = (n + 7) / 8;

    // CSR prologue (GEMM-independent parts first; hgemm placed 6th for ncu -s 5)
    preB_zcnt <<<196, 256>>>(W1, Wres, W2, n);                 // 1
    histo_kernel <<<(tot + 255) / 256, 256>>>(dst, E, n);      // 2
    scan1_kernel <<<nblk, 256>>>(n);                           // 3
    scan2_kernel <<<1, 32>>>(nblk, n);                         // 4
    scan3_kernel <<<(n + 255) / 256, 256>>>(n);                // 5
    hgemm128 <<<nb_gemm, 256, HG_SMEM>>>(x, p_xw, n, 0, as1, ad1);        // 6 (profiled)
    scatter_kernel <<<(tot + 255) / 256, 256>>>(src, dst, E, n);          // 7
    hgemm128 <<<nb_gemm, 256, HG_SMEM>>>(x, p_aux, n, 16384, nullptr, nullptr); // 8

    // ---- layer 1 aggregation ----
    agg128 <<<nb_warp, 256>>>(p_xw, b1, g1, be1, m1, v1, p_aux, p_h1, n);

    // ---- layer 2 ----
    hgemm128 <<<nb_gemm, 256, HG_SMEM>>>(p_h1, p_xw, n, 32768, as2, ad2);
    agg128 <<<nb_warp, 256>>>(p_xw, b2, g2, be2, m2, v2, p_h1, p_h2, n);

    // ---- layer 3 ----
    gemm40 <<<nb_warp, 256>>>(p_h2, W3, as3, ad3, p_aux, n);
    agg40  <<<nb_warp, 256>>>(p_aux, b3, (float*)d_out, n);
}

// round 7
// speedup vs baseline: 1.6827x; 1.0079x over previous
#include <cuda_runtime.h>
#include <cuda_fp16.h>
#include <mma.h>
using namespace nvcuda;

// Problem constants
#define MAXN 50000
#define MAXE 400000
#define MAXTOT (MAXN + MAXE)
#define GAT_EPS 1e-5f

// ------------------------- scratch (device globals) ------------------------
__device__ float g_xw  [MAXN * 128];
__device__ float g_aux [MAXN * 128];
__device__ float g_h1  [MAXN * 128];
__device__ float g_h2  [MAXN * 128];
__device__ float g_es  [MAXN * 4];
__device__ float g_ed  [MAXN * 4];
__device__ int   g_cnt [MAXN];
__device__ int   g_off [MAXN + 1];
__device__ int   g_cur [MAXN];
__device__ int   g_csr [MAXTOT + 8];
__device__ int   g_bsum[64];
__device__ __half g_Bh[3 * 16384];
__device__ __half g_Bl[3 * 16384];

// ------------------------- preB (+ fused zcnt) ------------------------------
__global__ void preB_zcnt(const float* __restrict__ W1, const float* __restrict__ Wres,
                          const float* __restrict__ W2, int n) {
    int i = blockIdx.x * blockDim.x + threadIdx.x;
    if (i < n) g_cnt[i] = 0;
    if (i >= 3 * 16384) return;
    const float* W = (i < 16384) ? W1 : (i < 32768 ? Wres : W2);
    float v = W[i & 16383];
    __half h = __float2half_rn(v);
    g_Bh[i] = h;
    g_Bl[i] = __float2half_rn(v - __half2float(h));
}

__global__ void histo_kernel(const int* __restrict__ dst, int E, int n) {
    int i = blockIdx.x * blockDim.x + threadIdx.x;
    if (i >= E + n) return;
    int dd = (i < E) ? dst[i] : (i - E);
    atomicAdd(&g_cnt[dd], 1);
}

__global__ void scan1_kernel(int n) {
    __shared__ int wsum[8];
    int tid = threadIdx.x;
    int base = blockIdx.x * 1024 + tid * 4;
    int c0 = (base + 0 < n) ? g_cnt[base + 0] : 0;
    int c1 = (base + 1 < n) ? g_cnt[base + 1] : 0;
    int c2 = (base + 2 < n) ? g_cnt[base + 2] : 0;
    int c3 = (base + 3 < n) ? g_cnt[base + 3] : 0;
    int t = c0 + c1 + c2 + c3;
    int lane = tid & 31, wid = tid >> 5;
    int incl = t;
    #pragma unroll
    for (int o = 1; o < 32; o <<= 1) {
        int v = __shfl_up_sync(0xffffffffu, incl, o);
        if (lane >= o) incl += v;
    }
    if (lane == 31) wsum[wid] = incl;
    __syncthreads();
    if (tid == 0) {
        int r = 0;
        #pragma unroll
        for (int k = 0; k < 8; k++) { int v = wsum[k]; wsum[k] = r; r += v; }
        g_bsum[blockIdx.x] = r;
    }
    __syncthreads();
    int run = wsum[wid] + incl - t;
    if (base + 0 < n) g_off[base + 0] = run; run += c0;
    if (base + 1 < n) g_off[base + 1] = run; run += c1;
    if (base + 2 < n) g_off[base + 2] = run; run += c2;
    if (base + 3 < n) g_off[base + 3] = run;
}

// scan2+scan3 fused: each block redundantly scans <=64 block sums in SMEM,
// then applies its (constant-per-block) offset. Block 0 also writes g_off[n].
__global__ void scan23_kernel(int nb, int n) {
    __shared__ int sboff[64];
    __shared__ int sgrand;
    int tid = threadIdx.x;
    if (tid < 32) {
        int lane = tid;
        int v0 = (lane < nb) ? g_bsum[lane] : 0;
        int v1 = (32 + lane < nb) ? g_bsum[32 + lane] : 0;
        int i0 = v0;
        #pragma unroll
        for (int o = 1; o < 32; o <<= 1) {
            int q = __shfl_up_sync(0xffffffffu, i0, o);
            if (lane >= o) i0 += q;
        }
        int tot0 = __shfl_sync(0xffffffffu, i0, 31);
        int i1 = v1;
        #pragma unroll
        for (int o = 1; o < 32; o <<= 1) {
            int q = __shfl_up_sync(0xffffffffu, i1, o);
            if (lane >= o) i1 += q;
        }
        i1 += tot0;
        sboff[lane] = i0 - v0;
        sboff[32 + lane] = i1 - v1;
        if (lane == 31) sgrand = i1;
    }
    __syncthreads();
    int i = blockIdx.x * blockDim.x + tid;
    if (i < n) {
        int o = g_off[i] + sboff[i >> 10];
        g_off[i] = o;
        g_cur[i] = o;
    }
    if (blockIdx.x == 0 && tid == 0) g_off[n] = sgrand;
}

__global__ void scatter_kernel(const int* __restrict__ src, const int* __restrict__ dst,
                               int E, int n) {
    int i = blockIdx.x * blockDim.x + threadIdx.x;
    if (i >= E + n) return;
    int ss, dd;
    if (i < E) { ss = src[i]; dd = dst[i]; }
    else       { ss = dd = i - E; }
    int p = atomicAdd(&g_cur[dd], 1);
    g_csr[p] = ss;
}

// ------------------------- dual WMMA GEMM (layer 1): xw & aux from same A ---
// 512 threads = 16 warps (4M x 4N over 256 output cols: cols 0-127 -> C1,
// 128-255 -> C2). K chunked by 64. fp16x3 split.
#define LDA2 72
#define LDB2 272
#define HGD_SMEM ((2 * 128 * LDA2 + 2 * 64 * LDB2) * 2)   // 106496 bytes

__global__ void __launch_bounds__(512, 1)
hgemm_dual(const float* __restrict__ A, float* __restrict__ C1, float* __restrict__ C2,
           int M, int boff1, int boff2,
           const float* __restrict__ a_s, const float* __restrict__ a_d) {
    extern __shared__ __half sm[];
    __half* sAh = sm;
    __half* sAl = sAh + 128 * LDA2;
    __half* sBh = sAl + 128 * LDA2;
    __half* sBl = sBh + 64 * LDB2;
    int tid = threadIdx.x;
    int wid = tid >> 5, lane = tid & 31;
    int wm = wid & 3, wn = wid >> 2;          // wn 0-3: 0,1 -> C1; 2,3 -> C2
    int mi = wn >> 1, nsub = wn & 1;
    int row0 = blockIdx.x * 128;

    wmma::fragment<wmma::accumulator, 16, 16, 16, float> acc[2][4];
    #pragma unroll
    for (int i = 0; i < 2; i++)
        #pragma unroll
        for (int j = 0; j < 4; j++)
            wmma::fill_fragment(acc[i][j], 0.f);

    #pragma unroll
    for (int kc = 0; kc < 2; kc++) {
        // A chunk [128 x 64] fp32 -> hi/lo half2 (4096 float2, 8 iters)
        #pragma unroll
        for (int it = 0; it < 8; it++) {
            int idx = tid + it * 512;
            int r = idx >> 5, c2 = idx & 31;
            int gr = row0 + r;
            float2 v = make_float2(0.f, 0.f);
            if (gr < M) v = *(const float2*)(A + (size_t)gr * 128 + kc * 64 + c2 * 2);
            __half hx = __float2half_rn(v.x), hy = __float2half_rn(v.y);
            *(__half2*)(sAh + r * LDA2 + c2 * 2) = __halves2half2(hx, hy);
            *(__half2*)(sAl + r * LDA2 + c2 * 2) =
                __halves2half2(__float2half_rn(v.x - __half2float(hx)),
                               __float2half_rn(v.y - __half2float(hy)));
        }
        // B chunk [64 x 256]: cols 0-127 from boff1 matrix, 128-255 from boff2
        #pragma unroll
        for (int it = 0; it < 16; it++) {
            int idx = tid + it * 512;             // 8192 half2
            int r = idx >> 7, c2 = idx & 127;
            int bm = c2 >> 6;                     // 0 -> B1, 1 -> B2
            int off = (bm ? boff2 : boff1) + (kc * 64 + r) * 128 + (c2 & 63) * 2;
            *(__half2*)(sBh + r * LDB2 + c2 * 2) = *(const __half2*)(g_Bh + off);
            *(__half2*)(sBl + r * LDB2 + c2 * 2) = *(const __half2*)(g_Bl + off);
        }
        __syncthreads();

        #pragma unroll
        for (int kk = 0; kk < 4; kk++) {
            wmma::fragment<wmma::matrix_a, 16, 16, 16, __half, wmma::row_major> ah[2], al[2];
            #pragma unroll
            for (int i = 0; i < 2; i++) {
                wmma::load_matrix_sync(ah[i], sAh + (wm * 32 + i * 16) * LDA2 + kk * 16, LDA2);
                wmma::load_matrix_sync(al[i], sAl + (wm * 32 + i * 16) * LDA2 + kk * 16, LDA2);
            }
            #pragma unroll
            for (int j = 0; j < 4; j++) {
                wmma::fragment<wmma::matrix_b, 16, 16, 16, __half, wmma::row_major> bh, bl;
                int cb = mi * 128 + nsub * 64 + j * 16;
                wmma::load_matrix_sync(bh, sBh + kk * 16 * LDB2 + cb, LDB2);
                wmma::load_matrix_sync(bl, sBl + kk * 16 * LDB2 + cb, LDB2);
                #pragma unroll
                for (int i = 0; i < 2; i++) {
                    wmma::mma_sync(acc[i][j], ah[i], bh, acc[i][j]);
                    wmma::mma_sync(acc[i][j], al[i], bh, acc[i][j]);
                    wmma::mma_sync(acc[i][j], ah[i], bl, acc[i][j]);
                }
            }
        }
        __syncthreads();
    }

    float* C = mi ? C2 : C1;
    #pragma unroll
    for (int i = 0; i < 2; i++) {
        int gr = row0 + wm * 32 + i * 16;
        if (gr < M) {
            #pragma unroll
            for (int j = 0; j < 4; j++)
                wmma::store_matrix_sync(C + (size_t)gr * 128 + nsub * 64 + j * 16,
                                        acc[i][j], 128, wmma::mem_row_major);
        }
    }

    // fused dots on C1 (xw): 16 warps x 8 rows
    __syncthreads();
    float4 asv = *(const float4*)(a_s + lane * 4);
    float4 adv = *(const float4*)(a_d + lane * 4);
    #pragma unroll
    for (int rr = 0; rr < 8; rr++) {
        int row = row0 + wid * 8 + rr;
        if (row >= M) break;
        float4 xv = *(const float4*)(C1 + (size_t)row * 128 + lane * 4);
        float ps = xv.x * asv.x + xv.y * asv.y + xv.z * asv.z + xv.w * asv.w;
        float pd = xv.x * adv.x + xv.y * adv.y + xv.z * adv.z + xv.w * adv.w;
        ps += __shfl_xor_sync(0xffffffffu, ps, 1);
        ps += __shfl_xor_sync(0xffffffffu, ps, 2);
        ps += __shfl_xor_sync(0xffffffffu, ps, 4);
        pd += __shfl_xor_sync(0xffffffffu, pd, 1);
        pd += __shfl_xor_sync(0xffffffffu, pd, 2);
        pd += __shfl_xor_sync(0xffffffffu, pd, 4);
        if ((lane & 7) == 0) {
            int h = lane >> 3;
            g_es[row * 4 + h] = ps;
            g_ed[row * 4 + h] = pd;
        }
    }
}

// ------------------------- single WMMA GEMM (layer 2) -----------------------
#define LDA 72
#define LDB 136
#define HG_SMEM ((2 * 128 * LDA + 2 * 64 * LDB) * 2)   // 71680 bytes

__global__ void __launch_bounds__(256, 2)
hgemm128(const float* __restrict__ A, float* __restrict__ C, int M, int boff,
         const float* __restrict__ a_s, const float* __restrict__ a_d) {
    extern __shared__ __half sm[];
    __half* sAh = sm;
    __half* sAl = sAh + 128 * LDA;
    __half* sBh = sAl + 128 * LDA;
    __half* sBl = sBh + 64 * LDB;
    int tid = threadIdx.x;
    int wid = tid >> 5, lane = tid & 31;
    int wm = wid & 3, wn = wid >> 2;
    int row0 = blockIdx.x * 128;

    wmma::fragment<wmma::accumulator, 16, 16, 16, float> acc[2][4];
    #pragma unroll
    for (int i = 0; i < 2; i++)
        #pragma unroll
        for (int j = 0; j < 4; j++)
            wmma::fill_fragment(acc[i][j], 0.f);

    #pragma unroll
    for (int kc = 0; kc < 2; kc++) {
        #pragma unroll
        for (int it = 0; it < 16; it++) {
            int idx = tid + it * 256;
            int r = idx >> 5, c2 = idx & 31;
            int gr = row0 + r;
            float2 v = make_float2(0.f, 0.f);
            if (gr < M) v = *(const float2*)(A + (size_t)gr * 128 + kc * 64 + c2 * 2);
            __half hx = __float2half_rn(v.x), hy = __float2half_rn(v.y);
            *(__half2*)(sAh + r * LDA + c2 * 2) = __halves2half2(hx, hy);
            *(__half2*)(sAl + r * LDA + c2 * 2) =
                __halves2half2(__float2half_rn(v.x - __half2float(hx)),
                               __float2half_rn(v.y - __half2float(hy)));
        }
        {
            const __half2* bh = (const __half2*)(g_Bh + boff + kc * 64 * 128);
            const __half2* bl = (const __half2*)(g_Bl + boff + kc * 64 * 128);
            #pragma unroll
            for (int it = 0; it < 16; it++) {
                int idx = tid + it * 256;
                int r = idx >> 6, c2 = idx & 63;
                *(__half2*)(sBh + r * LDB + c2 * 2) = bh[idx];
                *(__half2*)(sBl + r * LDB + c2 * 2) = bl[idx];
            }
        }
        __syncthreads();

        #pragma unroll
        for (int kk = 0; kk < 4; kk++) {
            wmma::fragment<wmma::matrix_a, 16, 16, 16, __half, wmma::row_major> ah[2], al[2];
            #pragma unroll
            for (int i = 0; i < 2; i++) {
                wmma::load_matrix_sync(ah[i], sAh + (wm * 32 + i * 16) * LDA + kk * 16, LDA);
                wmma::load_matrix_sync(al[i], sAl + (wm * 32 + i * 16) * LDA + kk * 16, LDA);
            }
            #pragma unroll
            for (int j = 0; j < 4; j++) {
                wmma::fragment<wmma::matrix_b, 16, 16, 16, __half, wmma::row_major> bh, bl;
                wmma::load_matrix_sync(bh, sBh + kk * 16 * LDB + wn * 64 + j * 16, LDB);
                wmma::load_matrix_sync(bl, sBl + kk * 16 * LDB + wn * 64 + j * 16, LDB);
                #pragma unroll
                for (int i = 0; i < 2; i++) {
                    wmma::mma_sync(acc[i][j], ah[i], bh, acc[i][j]);
                    wmma::mma_sync(acc[i][j], al[i], bh, acc[i][j]);
                    wmma::mma_sync(acc[i][j], ah[i], bl, acc[i][j]);
                }
            }
        }
        __syncthreads();
    }

    #pragma unroll
    for (int i = 0; i < 2; i++) {
        int gr = row0 + wm * 32 + i * 16;
        if (gr < M) {
            #pragma unroll
            for (int j = 0; j < 4; j++)
                wmma::store_matrix_sync(C + (size_t)gr * 128 + wn * 64 + j * 16,
                                        acc[i][j], 128, wmma::mem_row_major);
        }
    }

    if (a_s) {
        __syncthreads();
        float4 asv = *(const float4*)(a_s + lane * 4);
        float4 adv = *(const float4*)(a_d + lane * 4);
        #pragma unroll
        for (int rr = 0; rr < 16; rr++) {
            int row = row0 + wid * 16 + rr;
            if (row >= M) break;
            float4 xv = *(const float4*)(C + (size_t)row * 128 + lane * 4);
            float ps = xv.x * asv.x + xv.y * asv.y + xv.z * asv.z + xv.w * asv.w;
            float pd = xv.x * adv.x + xv.y * adv.y + xv.z * adv.z + xv.w * adv.w;
            ps += __shfl_xor_sync(0xffffffffu, ps, 1);
            ps += __shfl_xor_sync(0xffffffffu, ps, 2);
            ps += __shfl_xor_sync(0xffffffffu, ps, 4);
            pd += __shfl_xor_sync(0xffffffffu, pd, 1);
            pd += __shfl_xor_sync(0xffffffffu, pd, 2);
            pd += __shfl_xor_sync(0xffffffffu, pd, 4);
            if ((lane & 7) == 0) {
                int h = lane >> 3;
                g_es[row * 4 + h] = ps;
                g_ed[row * 4 + h] = pd;
            }
        }
    }
}

// ------------------------- layer-3 GEMM (40 cols) + fused dots --------------
__global__ void gemm40(const float* __restrict__ A, const float* __restrict__ B,
                       const float* __restrict__ a_s, const float* __restrict__ a_d,
                       float* __restrict__ C, int M) {
    __shared__ float Ws[128 * 40];
    for (int i = threadIdx.x; i < 128 * 40; i += blockDim.x) Ws[i] = B[i];
    __syncthreads();
    int row  = blockIdx.x * 8 + (threadIdx.x >> 5);
    int lane = threadIdx.x & 31;
    if (row >= M) return;
    const float* a = A + (size_t)row * 128;
    float acc1 = 0.f, acc2 = 0.f;
    #pragma unroll 8
    for (int k = 0; k < 128; k++) {
        float av = __ldg(a + k);
        acc1 += av * Ws[k * 40 + lane];
        if (lane < 8) acc2 += av * Ws[k * 40 + 32 + lane];
    }
    C[(size_t)row * 40 + lane] = acc1;
    if (lane < 8) C[(size_t)row * 40 + 32 + lane] = acc2;
    float ps = acc1 * a_s[lane] + ((lane < 8) ? acc2 * a_s[32 + lane] : 0.f);
    float pd = acc1 * a_d[lane] + ((lane < 8) ? acc2 * a_d[32 + lane] : 0.f);
    #pragma unroll
    for (int o = 16; o; o >>= 1) {
        ps += __shfl_xor_sync(0xffffffffu, ps, o);
        pd += __shfl_xor_sync(0xffffffffu, pd, o);
    }
    if (lane == 0) { g_es[row] = ps; g_ed[row] = pd; }
}

// ------------------------- fused GAT agg: stats + gather + BN/res/ELU -------
__global__ void agg128(const float* __restrict__ xw,
                       const float* __restrict__ bias,
                       const float* __restrict__ gam, const float* __restrict__ bet,
                       const float* __restrict__ mean, const float* __restrict__ var,
                       const float* __restrict__ res, float* __restrict__ out, int n) {
    int node = blockIdx.x * 8 + (threadIdx.x >> 5);
    if (node >= n) return;
    int lane = threadIdx.x & 31;
    int head = lane >> 3, esub = lane & 7;
    float ed = g_ed[node * 4 + head];
    int s = g_off[node], e = g_off[node + 1];

    float m = -1e30f, den = 0.f;
    for (int base = s; base < e; base += 8) {
        int i = base + esub;
        bool val = i < e;
        int u = val ? g_csr[i] : 0;
        float ev = g_es[u * 4 + head] + ed;
        ev = ev > 0.f ? ev : 0.2f * ev;
        if (!val) ev = -1e30f;
        float gm = ev;
        gm = fmaxf(gm, __shfl_xor_sync(0xffffffffu, gm, 1));
        gm = fmaxf(gm, __shfl_xor_sync(0xffffffffu, gm, 2));
        gm = fmaxf(gm, __shfl_xor_sync(0xffffffffu, gm, 4));
        float nm = fmaxf(m, gm);
        float w = __expf(ev - nm);
        w += __shfl_xor_sync(0xffffffffu, w, 1);
        w += __shfl_xor_sync(0xffffffffu, w, 2);
        w += __shfl_xor_sync(0xffffffffu, w, 4);
        den = den * __expf(m - nm) + w;
        m = nm;
    }
    float rinv = 1.f / den;

    float4 acc = make_float4(0.f, 0.f, 0.f, 0.f);
    int u = g_csr[s];
    for (int i = s; i < e; i++) {
        int un = g_csr[i + 1];
        float ev = g_es[u * 4 + head] + ed;
        ev = ev > 0.f ? ev : 0.2f * ev;
        float w = __expf(ev - m);
        float4 xv = *(const float4*)(xw + (size_t)u * 128 + lane * 4);
        acc.x += w * xv.x; acc.y += w * xv.y;
        acc.z += w * xv.z; acc.w += w * xv.w;
        u = un;
    }

    int c = lane * 4;
    float4 b4 = *(const float4*)(bias + c);
    float4 g4 = *(const float4*)(gam + c);
    float4 e4 = *(const float4*)(bet + c);
    float4 m4 = *(const float4*)(mean + c);
    float4 v4 = *(const float4*)(var + c);
    float4 r4 = *(const float4*)(res + (size_t)node * 128 + c);
    float o0 = (acc.x * rinv + b4.x - m4.x) * rsqrtf(v4.x + GAT_EPS) * g4.x + e4.x + r4.x;
    float o1 = (acc.y * rinv + b4.y - m4.y) * rsqrtf(v4.y + GAT_EPS) * g4.y + e4.y + r4.y;
    float o2 = (acc.z * rinv + b4.z - m4.z) * rsqrtf(v4.z + GAT_EPS) * g4.z + e4.z + r4.z;
    float o3 = (acc.w * rinv + b4.w - m4.w) * rsqrtf(v4.w + GAT_EPS) * g4.w + e4.w + r4.w;
    float4 o = make_float4(o0 > 0.f ? o0 : expm1f(o0),
                           o1 > 0.f ? o1 : expm1f(o1),
                           o2 > 0.f ? o2 : expm1f(o2),
                           o3 > 0.f ? o3 : expm1f(o3));
    *(float4*)(out + (size_t)node * 128 + c) = o;
}

// ------------------------- layer-3 agg (two-pass, branch-free) --------------
__global__ void agg40(const float* __restrict__ xw, const float* __restrict__ bias,
                      float* __restrict__ out, int n) {
    int node = blockIdx.x * 8 + (threadIdx.x >> 5);
    if (node >= n) return;
    int lane = threadIdx.x & 31;
    float ed = g_ed[node];
    int s = g_off[node], e = g_off[node + 1];

    float m = -1e30f, den = 0.f;
    for (int base = s; base < e; base += 32) {
        int i = base + lane;
        bool val = i < e;
        int u = val ? g_csr[i] : 0;
        float ev = g_es[u] + ed;
        ev = ev > 0.f ? ev : 0.2f * ev;
        if (!val) ev = -1e30f;
        float gm = ev;
        #pragma unroll
        for (int o = 16; o; o >>= 1) gm = fmaxf(gm, __shfl_xor_sync(0xffffffffu, gm, o));
        float nm = fmaxf(m, gm);
        float w = __expf(ev - nm);
        #pragma unroll
        for (int o = 16; o; o >>= 1) w += __shfl_xor_sync(0xffffffffu, w, o);
        den = den * __expf(m - nm) + w;
        m = nm;
    }
    float rinv = 1.f / den;

    float a1 = 0.f, a2 = 0.f;
    int u = g_csr[s];
    for (int i = s; i < e; i++) {
        int un = g_csr[i + 1];
        float ev = g_es[u] + ed;
        ev = ev > 0.f ? ev : 0.2f * ev;
        float w = __expf(ev - m);
        a1 += w * xw[(size_t)u * 40 + lane];
        if (lane < 8) a2 += w * xw[(size_t)u * 40 + 32 + lane];
        u = un;
    }
    out[(size_t)node * 40 + lane] = a1 * rinv + bias[lane];
    if (lane < 8) out[(size_t)node * 40 + 32 + lane] = a2 * rinv + bias[32 + lane];
}

// ------------------------- launch ------------------------------------------
extern "C" void kernel_launch(void* const* d_in, const int* in_sizes, int n_in,
                              void* d_out, int out_size) {
    const float* x    = (const float*)d_in[0];
    const int*   ei   = (const int*)  d_in[1];
    const float* W1   = (const float*)d_in[2];
    const float* as1  = (const float*)d_in[3];
    const float* ad1  = (const float*)d_in[4];
    const float* b1   = (const float*)d_in[5];
    const float* W2   = (const float*)d_in[6];
    const float* as2  = (const float*)d_in[7];
    const float* ad2  = (const float*)d_in[8];
    const float* b2   = (const float*)d_in[9];
    const float* W3   = (const float*)d_in[10];
    const float* as3  = (const float*)d_in[11];
    const float* ad3  = (const float*)d_in[12];
    const float* b3   = (const float*)d_in[13];
    const float* Wres = (const float*)d_in[14];
    const float* g1   = (const float*)d_in[15];
    const float* be1  = (const float*)d_in[16];
    const float* m1   = (const float*)d_in[17];
    const float* v1   = (const float*)d_in[18];
    const float* g2   = (const float*)d_in[19];
    const float* be2  = (const float*)d_in[20];
    const float* m2   = (const float*)d_in[21];
    const float* v2   = (const float*)d_in[22];

    int n = in_sizes[0] / 128;
    int E = in_sizes[1] / 2;
    const int* src = ei;
    const int* dst = ei + E;
    int tot = E + n;
    int nblk = (n + 1023) / 1024;

    float *p_xw, *p_aux, *p_h1, *p_h2;
    cudaGetSymbolAddress((void**)&p_xw,  g_xw);
    cudaGetSymbolAddress((void**)&p_aux, g_aux);
    cudaGetSymbolAddress((void**)&p_h1,  g_h1);
    cudaGetSymbolAddress((void**)&p_h2,  g_h2);

    cudaFuncSetAttribute(hgemm_dual, cudaFuncAttributeMaxDynamicSharedMemorySize, HGD_SMEM);
    cudaFuncSetAttribute(hgemm128,   cudaFuncAttributeMaxDynamicSharedMemorySize, HG_SMEM);

    int nb_gemm = (n + 127) / 128;
    int nb_warp = (n + 7) / 8;

    preB_zcnt <<<196, 256>>>(W1, Wres, W2, n);                             // 1
    histo_kernel <<<(tot + 255) / 256, 256>>>(dst, E, n);                  // 2
    scan1_kernel <<<nblk, 256>>>(n);                                       // 3
    hgemm_dual <<<nb_gemm, 512, HGD_SMEM>>>(x, p_xw, p_aux, n, 0, 16384, as1, ad1); // 4 (profiled)
    scan23_kernel <<<(n + 255) / 256, 256>>>(nblk, n);                     // 5
    scatter_kernel <<<(tot + 255) / 256, 256>>>(src, dst, E, n);           // 6

    // ---- layer 1 aggregation ----
    agg128 <<<nb_warp, 256>>>(p_xw, b1, g1, be1, m1, v1, p_aux, p_h1, n);  // 7

    // ---- layer 2 ----
    hgemm128 <<<nb_gemm, 256, HG_SMEM>>>(p_h1, p_xw, n, 32768, as2, ad2);  // 8
    agg128 <<<nb_warp, 256>>>(p_xw, b2, g2, be2, m2, v2, p_h1, p_h2, n);   // 9

    // ---- layer 3 ----
    gemm40 <<<nb_warp, 256>>>(p_h2, W3, as3, ad3, p_aux, n);               // 10
    agg40  <<<nb_warp, 256>>>(p_aux, b3, (float*)d_out, n);                // 11
}

// round 8
// speedup vs baseline: 1.7308x; 1.0286x over previous
#include <cuda_runtime.h>
#include <cuda_fp16.h>
#include <mma.h>
using namespace nvcuda;

// Problem constants
#define MAXN 50000
#define MAXE 400000
#define MAXTOT (MAXN + MAXE)
#define GAT_EPS 1e-5f

// ------------------------- scratch (device globals) ------------------------
__device__ float g_xw  [MAXN * 128];
__device__ float g_aux [MAXN * 128];
__device__ float g_h1  [MAXN * 128];
__device__ float g_h2  [MAXN * 128];
__device__ float g_es  [MAXN * 4];
__device__ float g_ed  [MAXN * 4];
__device__ int   g_cnt [MAXN];
__device__ int   g_off [MAXN + 1];
__device__ int   g_cur [MAXN];
__device__ int   g_csr [MAXTOT + 8];
__device__ int   g_bsum[64];
__device__ __align__(16) __half g_Bh[3 * 16384];
__device__ __align__(16) __half g_Bl[3 * 16384];

// ------------------------- preB (+ fused zcnt) ------------------------------
__global__ void preB_zcnt(const float* __restrict__ W1, const float* __restrict__ Wres,
                          const float* __restrict__ W2, int n) {
    int i = blockIdx.x * blockDim.x + threadIdx.x;
    if (i < n) g_cnt[i] = 0;
    if (i >= 3 * 16384) return;
    const float* W = (i < 16384) ? W1 : (i < 32768 ? Wres : W2);
    float v = W[i & 16383];
    __half h = __float2half_rn(v);
    g_Bh[i] = h;
    g_Bl[i] = __float2half_rn(v - __half2float(h));
}

__global__ void histo_kernel(const int* __restrict__ dst, int E, int n) {
    int i = blockIdx.x * blockDim.x + threadIdx.x;
    if (i >= E + n) return;
    int dd = (i < E) ? dst[i] : (i - E);
    atomicAdd(&g_cnt[dd], 1);
}

__global__ void scan1_kernel(int n) {
    __shared__ int wsum[8];
    int tid = threadIdx.x;
    int base = blockIdx.x * 1024 + tid * 4;
    int c0 = (base + 0 < n) ? g_cnt[base + 0] : 0;
    int c1 = (base + 1 < n) ? g_cnt[base + 1] : 0;
    int c2 = (base + 2 < n) ? g_cnt[base + 2] : 0;
    int c3 = (base + 3 < n) ? g_cnt[base + 3] : 0;
    int t = c0 + c1 + c2 + c3;
    int lane = tid & 31, wid = tid >> 5;
    int incl = t;
    #pragma unroll
    for (int o = 1; o < 32; o <<= 1) {
        int v = __shfl_up_sync(0xffffffffu, incl, o);
        if (lane >= o) incl += v;
    }
    if (lane == 31) wsum[wid] = incl;
    __syncthreads();
    if (tid == 0) {
        int r = 0;
        #pragma unroll
        for (int k = 0; k < 8; k++) { int v = wsum[k]; wsum[k] = r; r += v; }
        g_bsum[blockIdx.x] = r;
    }
    __syncthreads();
    int run = wsum[wid] + incl - t;
    if (base + 0 < n) g_off[base + 0] = run; run += c0;
    if (base + 1 < n) g_off[base + 1] = run; run += c1;
    if (base + 2 < n) g_off[base + 2] = run; run += c2;
    if (base + 3 < n) g_off[base + 3] = run;
}

__global__ void scan23_kernel(int nb, int n) {
    __shared__ int sboff[64];
    __shared__ int sgrand;
    int tid = threadIdx.x;
    if (tid < 32) {
        int lane = tid;
        int v0 = (lane < nb) ? g_bsum[lane] : 0;
        int v1 = (32 + lane < nb) ? g_bsum[32 + lane] : 0;
        int i0 = v0;
        #pragma unroll
        for (int o = 1; o < 32; o <<= 1) {
            int q = __shfl_up_sync(0xffffffffu, i0, o);
            if (lane >= o) i0 += q;
        }
        int tot0 = __shfl_sync(0xffffffffu, i0, 31);
        int i1 = v1;
        #pragma unroll
        for (int o = 1; o < 32; o <<= 1) {
            int q = __shfl_up_sync(0xffffffffu, i1, o);
            if (lane >= o) i1 += q;
        }
        i1 += tot0;
        sboff[lane] = i0 - v0;
        sboff[32 + lane] = i1 - v1;
        if (lane == 31) sgrand = i1;
    }
    __syncthreads();
    int i = blockIdx.x * blockDim.x + tid;
    if (i < n) {
        int o = g_off[i] + sboff[i >> 10];
        g_off[i] = o;
        g_cur[i] = o;
    }
    if (blockIdx.x == 0 && tid == 0) g_off[n] = sgrand;
}

__global__ void scatter_kernel(const int* __restrict__ src, const int* __restrict__ dst,
                               int E, int n) {
    int i = blockIdx.x * blockDim.x + threadIdx.x;
    if (i >= E + n) return;
    int ss, dd;
    if (i < E) { ss = src[i]; dd = dst[i]; }
    else       { ss = dd = i - E; }
    int p = atomicAdd(&g_cur[dd], 1);
    g_csr[p] = ss;
}

// ------------------------- GEMM helpers -------------------------------------
#define LDAH 136                                // half stride, A (128 K + 8 pad)
#define LDBH 272                                // half stride, B dual (256 N + 16 pad)
#define LDBS 136                                // half stride, B single
#define SM_DUAL ((2 * 128 * LDBH + 2 * 128 * LDAH) * 2)   // 208896 B
#define SM_SNGL ((2 * 128 * LDBS + 2 * 128 * LDAH) * 2)   // 139264 B

__device__ __forceinline__ void cp16(__half* dst, const __half* src) {
    unsigned d = (unsigned)__cvta_generic_to_shared(dst);
    asm volatile("cp.async.cg.shared.global [%0], [%1], 16;\n" :: "r"(d), "l"(src));
}

// ------------------------- dual WMMA GEMM (layer 1) -------------------------
// 512 threads, whole K resident, one sync. Warp w: wm=w&3 (32-row band),
// wn=w>>2 (64-col band of 256 cols = [C1 | C2]).
__global__ void __launch_bounds__(512, 1)
hgemm_dual(const float* __restrict__ A, float* __restrict__ C1, float* __restrict__ C2,
           int M, int boff1, int boff2,
           const float* __restrict__ a_s, const float* __restrict__ a_d) {
    extern __shared__ __half sm[];
    __half* sBh = sm;
    __half* sBl = sBh + 128 * LDBH;
    __half* sAh = sBl + 128 * LDBH;
    __half* sAl = sAh + 128 * LDAH;
    int tid = threadIdx.x;
    int wid = tid >> 5, lane = tid & 31;
    int wm = wid & 3, wn = wid >> 2;
    int mi = wn >> 1, nsub = wn & 1;
    int row0 = blockIdx.x * 128;

    // B: 8192 16B chunks via cp.async (no conversion needed)
    #pragma unroll
    for (int it = 0; it < 16; it++) {
        int idx = tid + it * 512;
        int c4 = idx & 15, row = (idx >> 4) & 127, mat = (idx >> 11) & 1, hl = idx >> 12;
        const __half* src = (hl ? g_Bl : g_Bh) + (mat ? boff2 : boff1) + row * 128 + c4 * 8;
        __half* dst = (hl ? sBl : sBh) + row * LDBH + mat * 128 + c4 * 8;
        cp16(dst, src);
    }
    asm volatile("cp.async.commit_group;\n");

    // A: load fp32, split to hi/lo fp16 (overlaps with B cp.async)
    #pragma unroll
    for (int it = 0; it < 16; it++) {
        int idx = tid + it * 512;
        int c2 = idx & 63, r = idx >> 6;
        int gr = row0 + r;
        float2 v = make_float2(0.f, 0.f);
        if (gr < M) v = *(const float2*)(A + (size_t)gr * 128 + c2 * 2);
        __half hx = __float2half_rn(v.x), hy = __float2half_rn(v.y);
        *(__half2*)(sAh + r * LDAH + c2 * 2) = __halves2half2(hx, hy);
        *(__half2*)(sAl + r * LDAH + c2 * 2) =
            __halves2half2(__float2half_rn(v.x - __half2float(hx)),
                           __float2half_rn(v.y - __half2float(hy)));
    }
    asm volatile("cp.async.wait_group 0;\n");
    __syncthreads();

    wmma::fragment<wmma::accumulator, 16, 16, 16, float> acc[2][4];
    #pragma unroll
    for (int i = 0; i < 2; i++)
        #pragma unroll
        for (int j = 0; j < 4; j++)
            wmma::fill_fragment(acc[i][j], 0.f);

    #pragma unroll
    for (int kk = 0; kk < 8; kk++) {
        wmma::fragment<wmma::matrix_a, 16, 16, 16, __half, wmma::row_major> ah[2], al[2];
        #pragma unroll
        for (int i = 0; i < 2; i++) {
            wmma::load_matrix_sync(ah[i], sAh + (wm * 32 + i * 16) * LDAH + kk * 16, LDAH);
            wmma::load_matrix_sync(al[i], sAl + (wm * 32 + i * 16) * LDAH + kk * 16, LDAH);
        }
        #pragma unroll
        for (int j = 0; j < 4; j++) {
            wmma::fragment<wmma::matrix_b, 16, 16, 16, __half, wmma::row_major> bh, bl;
            wmma::load_matrix_sync(bh, sBh + kk * 16 * LDBH + wn * 64 + j * 16, LDBH);
            wmma::load_matrix_sync(bl, sBl + kk * 16 * LDBH + wn * 64 + j * 16, LDBH);
            #pragma unroll
            for (int i = 0; i < 2; i++) {
                wmma::mma_sync(acc[i][j], ah[i], bh, acc[i][j]);
                wmma::mma_sync(acc[i][j], al[i], bh, acc[i][j]);
                wmma::mma_sync(acc[i][j], ah[i], bl, acc[i][j]);
            }
        }
    }

    float* C = mi ? C2 : C1;
    #pragma unroll
    for (int i = 0; i < 2; i++) {
        int gr = row0 + wm * 32 + i * 16;
        if (gr < M) {
            #pragma unroll
            for (int j = 0; j < 4; j++)
                wmma::store_matrix_sync(C + (size_t)gr * 128 + nsub * 64 + j * 16,
                                        acc[i][j], 128, wmma::mem_row_major);
        }
    }

    // fused dots on C1 (xw): 16 warps x 8 rows
    __syncthreads();
    float4 asv = *(const float4*)(a_s + lane * 4);
    float4 adv = *(const float4*)(a_d + lane * 4);
    #pragma unroll
    for (int rr = 0; rr < 8; rr++) {
        int row = row0 + wid * 8 + rr;
        if (row >= M) break;
        float4 xv = *(const float4*)(C1 + (size_t)row * 128 + lane * 4);
        float ps = xv.x * asv.x + xv.y * asv.y + xv.z * asv.z + xv.w * asv.w;
        float pd = xv.x * adv.x + xv.y * adv.y + xv.z * adv.z + xv.w * adv.w;
        ps += __shfl_xor_sync(0xffffffffu, ps, 1);
        ps += __shfl_xor_sync(0xffffffffu, ps, 2);
        ps += __shfl_xor_sync(0xffffffffu, ps, 4);
        pd += __shfl_xor_sync(0xffffffffu, pd, 1);
        pd += __shfl_xor_sync(0xffffffffu, pd, 2);
        pd += __shfl_xor_sync(0xffffffffu, pd, 4);
        if ((lane & 7) == 0) {
            int h = lane >> 3;
            g_es[row * 4 + h] = ps;
            g_ed[row * 4 + h] = pd;
        }
    }
}

// ------------------------- single WMMA GEMM (layer 2) -----------------------
// 512 threads, warp tile 32x32 over 128 cols, whole K resident, one sync.
__global__ void __launch_bounds__(512, 1)
hgemm128(const float* __restrict__ A, float* __restrict__ C, int M, int boff,
         const float* __restrict__ a_s, const float* __restrict__ a_d) {
    extern __shared__ __half sm[];
    __half* sBh = sm;
    __half* sBl = sBh + 128 * LDBS;
    __half* sAh = sBl + 128 * LDBS;
    __half* sAl = sAh + 128 * LDAH;
    int tid = threadIdx.x;
    int wid = tid >> 5, lane = tid & 31;
    int wm = wid & 3, wn = wid >> 2;
    int row0 = blockIdx.x * 128;

    // B: 4096 16B chunks
    #pragma unroll
    for (int it = 0; it < 8; it++) {
        int idx = tid + it * 512;
        int c4 = idx & 15, row = (idx >> 4) & 127, hl = idx >> 11;
        const __half* src = (hl ? g_Bl : g_Bh) + boff + row * 128 + c4 * 8;
        __half* dst = (hl ? sBl : sBh) + row * LDBS + c4 * 8;
        cp16(dst, src);
    }
    asm volatile("cp.async.commit_group;\n");

    #pragma unroll
    for (int it = 0; it < 16; it++) {
        int idx = tid + it * 512;
        int c2 = idx & 63, r = idx >> 6;
        int gr = row0 + r;
        float2 v = make_float2(0.f, 0.f);
        if (gr < M) v = *(const float2*)(A + (size_t)gr * 128 + c2 * 2);
        __half hx = __float2half_rn(v.x), hy = __float2half_rn(v.y);
        *(__half2*)(sAh + r * LDAH + c2 * 2) = __halves2half2(hx, hy);
        *(__half2*)(sAl + r * LDAH + c2 * 2) =
            __halves2half2(__float2half_rn(v.x - __half2float(hx)),
                           __float2half_rn(v.y - __half2float(hy)));
    }
    asm volatile("cp.async.wait_group 0;\n");
    __syncthreads();

    wmma::fragment<wmma::accumulator, 16, 16, 16, float> acc[2][2];
    #pragma unroll
    for (int i = 0; i < 2; i++)
        #pragma unroll
        for (int j = 0; j < 2; j++)
            wmma::fill_fragment(acc[i][j], 0.f);

    #pragma unroll
    for (int kk = 0; kk < 8; kk++) {
        wmma::fragment<wmma::matrix_a, 16, 16, 16, __half, wmma::row_major> ah[2], al[2];
        #pragma unroll
        for (int i = 0; i < 2; i++) {
            wmma::load_matrix_sync(ah[i], sAh + (wm * 32 + i * 16) * LDAH + kk * 16, LDAH);
            wmma::load_matrix_sync(al[i], sAl + (wm * 32 + i * 16) * LDAH + kk * 16, LDAH);
        }
        #pragma unroll
        for (int j = 0; j < 2; j++) {
            wmma::fragment<wmma::matrix_b, 16, 16, 16, __half, wmma::row_major> bh, bl;
            wmma::load_matrix_sync(bh, sBh + kk * 16 * LDBS + wn * 32 + j * 16, LDBS);
            wmma::load_matrix_sync(bl, sBl + kk * 16 * LDBS + wn * 32 + j * 16, LDBS);
            #pragma unroll
            for (int i = 0; i < 2; i++) {
                wmma::mma_sync(acc[i][j], ah[i], bh, acc[i][j]);
                wmma::mma_sync(acc[i][j], al[i], bh, acc[i][j]);
                wmma::mma_sync(acc[i][j], ah[i], bl, acc[i][j]);
            }
        }
    }

    #pragma unroll
    for (int i = 0; i < 2; i++) {
        int gr = row0 + wm * 32 + i * 16;
        if (gr < M) {
            #pragma unroll
            for (int j = 0; j < 2; j++)
                wmma::store_matrix_sync(C + (size_t)gr * 128 + wn * 32 + j * 16,
                                        acc[i][j], 128, wmma::mem_row_major);
        }
    }

    if (a_s) {
        __syncthreads();
        float4 asv = *(const float4*)(a_s + lane * 4);
        float4 adv = *(const float4*)(a_d + lane * 4);
        #pragma unroll
        for (int rr = 0; rr < 8; rr++) {
            int row = row0 + wid * 8 + rr;
            if (row >= M) break;
            float4 xv = *(const float4*)(C + (size_t)row * 128 + lane * 4);
            float ps = xv.x * asv.x + xv.y * asv.y + xv.z * asv.z + xv.w * asv.w;
            float pd = xv.x * adv.x + xv.y * adv.y + xv.z * adv.z + xv.w * adv.w;
            ps += __shfl_xor_sync(0xffffffffu, ps, 1);
            ps += __shfl_xor_sync(0xffffffffu, ps, 2);
            ps += __shfl_xor_sync(0xffffffffu, ps, 4);
            pd += __shfl_xor_sync(0xffffffffu, pd, 1);
            pd += __shfl_xor_sync(0xffffffffu, pd, 2);
            pd += __shfl_xor_sync(0xffffffffu, pd, 4);
            if ((lane & 7) == 0) {
                int h = lane >> 3;
                g_es[row * 4 + h] = ps;
                g_ed[row * 4 + h] = pd;
            }
        }
    }
}

// ------------------------- layer-3 GEMM (40 cols) + fused dots --------------
__global__ void gemm40(const float* __restrict__ A, const float* __restrict__ B,
                       const float* __restrict__ a_s, const float* __restrict__ a_d,
                       float* __restrict__ C, int M) {
    __shared__ float Ws[128 * 40];
    for (int i = threadIdx.x; i < 128 * 40; i += blockDim.x) Ws[i] = B[i];
    __syncthreads();
    int row  = blockIdx.x * 8 + (threadIdx.x >> 5);
    int lane = threadIdx.x & 31;
    if (row >= M) return;
    const float* a = A + (size_t)row * 128;
    float acc1 = 0.f, acc2 = 0.f;
    #pragma unroll 8
    for (int k = 0; k < 128; k++) {
        float av = __ldg(a + k);
        acc1 += av * Ws[k * 40 + lane];
        if (lane < 8) acc2 += av * Ws[k * 40 + 32 + lane];
    }
    C[(size_t)row * 40 + lane] = acc1;
    if (lane < 8) C[(size_t)row * 40 + 32 + lane] = acc2;
    float ps = acc1 * a_s[lane] + ((lane < 8) ? acc2 * a_s[32 + lane] : 0.f);
    float pd = acc1 * a_d[lane] + ((lane < 8) ? acc2 * a_d[32 + lane] : 0.f);
    #pragma unroll
    for (int o = 16; o; o >>= 1) {
        ps += __shfl_xor_sync(0xffffffffu, ps, o);
        pd += __shfl_xor_sync(0xffffffffu, pd, o);
    }
    if (lane == 0) { g_es[row] = ps; g_ed[row] = pd; }
}

// ------------------------- fused GAT agg: stats + gather + BN/res/ELU -------
__global__ void agg128(const float* __restrict__ xw,
                       const float* __restrict__ bias,
                       const float* __restrict__ gam, const float* __restrict__ bet,
                       const float* __restrict__ mean, const float* __restrict__ var,
                       const float* __restrict__ res, float* __restrict__ out, int n) {
    int node = blockIdx.x * 8 + (threadIdx.x >> 5);
    if (node >= n) return;
    int lane = threadIdx.x & 31;
    int head = lane >> 3, esub = lane & 7;
    float ed = g_ed[node * 4 + head];
    int s = g_off[node], e = g_off[node + 1];

    float m = -1e30f, den = 0.f;
    for (int base = s; base < e; base += 8) {
        int i = base + esub;
        bool val = i < e;
        int u = val ? g_csr[i] : 0;
        float ev = g_es[u * 4 + head] + ed;
        ev = ev > 0.f ? ev : 0.2f * ev;
        if (!val) ev = -1e30f;
        float gm = ev;
        gm = fmaxf(gm, __shfl_xor_sync(0xffffffffu, gm, 1));
        gm = fmaxf(gm, __shfl_xor_sync(0xffffffffu, gm, 2));
        gm = fmaxf(gm, __shfl_xor_sync(0xffffffffu, gm, 4));
        float nm = fmaxf(m, gm);
        float w = __expf(ev - nm);
        w += __shfl_xor_sync(0xffffffffu, w, 1);
        w += __shfl_xor_sync(0xffffffffu, w, 2);
        w += __shfl_xor_sync(0xffffffffu, w, 4);
        den = den * __expf(m - nm) + w;
        m = nm;
    }
    float rinv = 1.f / den;

    float4 acc = make_float4(0.f, 0.f, 0.f, 0.f);
    int u = g_csr[s];
    for (int i = s; i < e; i++) {
        int un = g_csr[i + 1];
        float ev = g_es[u * 4 + head] + ed;
        ev = ev > 0.f ? ev : 0.2f * ev;
        float w = __expf(ev - m);
        float4 xv = *(const float4*)(xw + (size_t)u * 128 + lane * 4);
        acc.x += w * xv.x; acc.y += w * xv.y;
        acc.z += w * xv.z; acc.w += w * xv.w;
        u = un;
    }

    int c = lane * 4;
    float4 b4 = *(const float4*)(bias + c);
    float4 g4 = *(const float4*)(gam + c);
    float4 e4 = *(const float4*)(bet + c);
    float4 m4 = *(const float4*)(mean + c);
    float4 v4 = *(const float4*)(var + c);
    float4 r4 = *(const float4*)(res + (size_t)node * 128 + c);
    float o0 = (acc.x * rinv + b4.x - m4.x) * rsqrtf(v4.x + GAT_EPS) * g4.x + e4.x + r4.x;
    float o1 = (acc.y * rinv + b4.y - m4.y) * rsqrtf(v4.y + GAT_EPS) * g4.y + e4.y + r4.y;
    float o2 = (acc.z * rinv + b4.z - m4.z) * rsqrtf(v4.z + GAT_EPS) * g4.z + e4.z + r4.z;
    float o3 = (acc.w * rinv + b4.w - m4.w) * rsqrtf(v4.w + GAT_EPS) * g4.w + e4.w + r4.w;
    float4 o = make_float4(o0 > 0.f ? o0 : expm1f(o0),
                           o1 > 0.f ? o1 : expm1f(o1),
                           o2 > 0.f ? o2 : expm1f(o2),
                           o3 > 0.f ? o3 : expm1f(o3));
    *(float4*)(out + (size_t)node * 128 + c) = o;
}

// ------------------------- layer-3 agg (two-pass, branch-free) --------------
__global__ void agg40(const float* __restrict__ xw, const float* __restrict__ bias,
                      float* __restrict__ out, int n) {
    int node = blockIdx.x * 8 + (threadIdx.x >> 5);
    if (node >= n) return;
    int lane = threadIdx.x & 31;
    float ed = g_ed[node];
    int s = g_off[node], e = g_off[node + 1];

    float m = -1e30f, den = 0.f;
    for (int base = s; base < e; base += 32) {
        int i = base + lane;
        bool val = i < e;
        int u = val ? g_csr[i] : 0;
        float ev = g_es[u] + ed;
        ev = ev > 0.f ? ev : 0.2f * ev;
        if (!val) ev = -1e30f;
        float gm = ev;
        #pragma unroll
        for (int o = 16; o; o >>= 1) gm = fmaxf(gm, __shfl_xor_sync(0xffffffffu, gm, o));
        float nm = fmaxf(m, gm);
        float w = __expf(ev - nm);
        #pragma unroll
        for (int o = 16; o; o >>= 1) w += __shfl_xor_sync(0xffffffffu, w, o);
        den = den * __expf(m - nm) + w;
        m = nm;
    }
    float rinv = 1.f / den;

    float a1 = 0.f, a2 = 0.f;
    int u = g_csr[s];
    for (int i = s; i < e; i++) {
        int un = g_csr[i + 1];
        float ev = g_es[u] + ed;
        ev = ev > 0.f ? ev : 0.2f * ev;
        float w = __expf(ev - m);
        a1 += w * xw[(size_t)u * 40 + lane];
        if (lane < 8) a2 += w * xw[(size_t)u * 40 + 32 + lane];
        u = un;
    }
    out[(size_t)node * 40 + lane] = a1 * rinv + bias[lane];
    if (lane < 8) out[(size_t)node * 40 + 32 + lane] = a2 * rinv + bias[32 + lane];
}

// ------------------------- launch ------------------------------------------
extern "C" void kernel_launch(void* const* d_in, const int* in_sizes, int n_in,
                              void* d_out, int out_size) {
    const float* x    = (const float*)d_in[0];
    const int*   ei   = (const int*)  d_in[1];
    const float* W1   = (const float*)d_in[2];
    const float* as1  = (const float*)d_in[3];
    const float* ad1  = (const float*)d_in[4];
    const float* b1   = (const float*)d_in[5];
    const float* W2   = (const float*)d_in[6];
    const float* as2  = (const float*)d_in[7];
    const float* ad2  = (const float*)d_in[8];
    const float* b2   = (const float*)d_in[9];
    const float* W3   = (const float*)d_in[10];
    const float* as3  = (const float*)d_in[11];
    const float* ad3  = (const float*)d_in[12];
    const float* b3   = (const float*)d_in[13];
    const float* Wres = (const float*)d_in[14];
    const float* g1   = (const float*)d_in[15];
    const float* be1  = (const float*)d_in[16];
    const float* m1   = (const float*)d_in[17];
    const float* v1   = (const float*)d_in[18];
    const float* g2   = (const float*)d_in[19];
    const float* be2  = (const float*)d_in[20];
    const float* m2   = (const float*)d_in[21];
    const float* v2   = (const float*)d_in[22];

    int n = in_sizes[0] / 128;
    int E = in_sizes[1] / 2;
    const int* src = ei;
    const int* dst = ei + E;
    int tot = E + n;
    int nblk = (n + 1023) / 1024;

    float *p_xw, *p_aux, *p_h1, *p_h2;
    cudaGetSymbolAddress((void**)&p_xw,  g_xw);
    cudaGetSymbolAddress((void**)&p_aux, g_aux);
    cudaGetSymbolAddress((void**)&p_h1,  g_h1);
    cudaGetSymbolAddress((void**)&p_h2,  g_h2);

    cudaFuncSetAttribute(hgemm_dual, cudaFuncAttributeMaxDynamicSharedMemorySize, SM_DUAL);
    cudaFuncSetAttribute(hgemm128,   cudaFuncAttributeMaxDynamicSharedMemorySize, SM_SNGL);

    int nb_gemm = (n + 127) / 128;
    int nb_warp = (n + 7) / 8;

    preB_zcnt <<<196, 256>>>(W1, Wres, W2, n);                             // 1
    histo_kernel <<<(tot + 255) / 256, 256>>>(dst, E, n);                  // 2
    scan1_kernel <<<nblk, 256>>>(n);                                       // 3
    hgemm_dual <<<nb_gemm, 512, SM_DUAL>>>(x, p_xw, p_aux, n, 0, 16384, as1, ad1); // 4 (profiled)
    scan23_kernel <<<(n + 255) / 256, 256>>>(nblk, n);                     // 5
    scatter_kernel <<<(tot + 255) / 256, 256>>>(src, dst, E, n);           // 6

    // ---- layer 1 aggregation ----
    agg128 <<<nb_warp, 256>>>(p_xw, b1, g1, be1, m1, v1, p_aux, p_h1, n);  // 7

    // ---- layer 2 ----
    hgemm128 <<<nb_gemm, 512, SM_SNGL>>>(p_h1, p_xw, n, 32768, as2, ad2);  // 8
    agg128 <<<nb_warp, 256>>>(p_xw, b2, g2, be2, m2, v2, p_h1, p_h2, n);   // 9

    // ---- layer 3 ----
    gemm40 <<<nb_warp, 256>>>(p_h2, W3, as3, ad3, p_aux, n);               // 10
    agg40  <<<nb_warp, 256>>>(p_aux, b3, (float*)d_out, n);                // 11
}